// round 13
// baseline (speedup 1.0000x reference)
#include <cuda_runtime.h>
#include <cuda_fp16.h>
#include <cstdint>

#define BB 128
#define SS 50
#define XX 128
#define HH 256
#define VV 10000
#define MM (BB*SS)     // 6400
#define NT_N 79
#define NPAD (NT_N * 128)   // 10112
#define N_TICKETS (SS * NT_N)

// ---------------- device scratch (no allocs allowed in kernel_launch) ------
__device__ float g_xin[MM * HH];                         // input projection [b][t][j]
__device__ float g_WT[HH * HH];                          // W_hh transposed: [k][j]
// t-MAJOR: row m = t*128 + b ; [m][0:256]=hi, [256:512]=lo  (fp16 split of h)
__device__ __align__(16) __half g_A2[MM * 512];
__device__ __align__(16) __half g_B2[(size_t)NPAD * 256];   // W_aff in plain fp16
__device__ int g_prog[SS];                               // per-step producer arrivals
__device__ int g_ticket;                                 // persistent consumer tickets

// ---------------- packed fp32x2 helpers --------------------------------------
__device__ __forceinline__ double dup2(float x) {
    double r; asm("mov.b64 %0, {%1, %1};" : "=d"(r) : "f"(x)); return r;
}
__device__ __forceinline__ double pk2(float lo, float hi) {
    double r; asm("mov.b64 %0, {%1, %2};" : "=d"(r) : "f"(lo), "f"(hi)); return r;
}
__device__ __forceinline__ float2 unpk(double d) {
    float2 f; asm("mov.b64 {%0, %1}, %2;" : "=f"(f.x), "=f"(f.y) : "d"(d)); return f;
}
__device__ __forceinline__ void ffma2(double& acc, double a, double b) {
    asm("fma.rn.f32x2 %0, %1, %2, %0;" : "+d"(acc) : "d"(a), "d"(b));
}
__device__ __forceinline__ double fadd2(double a, double b) {
    double r; asm("add.rn.f32x2 %0, %1, %2;" : "=d"(r) : "d"(a), "d"(b)); return r;
}

// ---------------- mma / smem helpers ------------------------------------------
__device__ __forceinline__ uint32_t smem_u32(const void* p) {
    uint32_t a;
    asm("{ .reg .u64 t; cvta.to.shared.u64 t, %1; cvt.u32.u64 %0, t; }" : "=r"(a) : "l"(p));
    return a;
}
__device__ __forceinline__ void cp_async16(uint32_t dst, const void* src) {
    asm volatile("cp.async.cg.shared.global [%0], [%1], 16;"
                 :: "r"(dst), "l"(src) : "memory");
}
__device__ __forceinline__ void ldsm4(uint32_t r[4], uint32_t addr) {
    asm volatile("ldmatrix.sync.aligned.m8n8.x4.shared.b16 {%0,%1,%2,%3}, [%4];"
                 : "=r"(r[0]), "=r"(r[1]), "=r"(r[2]), "=r"(r[3]) : "r"(addr));
}
__device__ __forceinline__ void mma16816(float c[4], const uint32_t a[4],
                                         uint32_t b0, uint32_t b1) {
    asm volatile(
        "mma.sync.aligned.m16n8k16.row.col.f32.f16.f16.f32 "
        "{%0,%1,%2,%3}, {%4,%5,%6,%7}, {%8,%9}, {%0,%1,%2,%3};"
        : "+f"(c[0]), "+f"(c[1]), "+f"(c[2]), "+f"(c[3])
        : "r"(a[0]), "r"(a[1]), "r"(a[2]), "r"(a[3]), "r"(b0), "r"(b1));
}
__device__ __forceinline__ int ld_acq(const int* p) {
    int v; asm volatile("ld.acquire.gpu.global.b32 %0, [%1];" : "=r"(v) : "l"(p)); return v;
}
__device__ __forceinline__ void red_release(int* p) {
    asm volatile("red.release.gpu.global.add.s32 [%0], %1;" :: "l"(p), "r"(1) : "memory");
}
#define SW128(x) ((x) ^ (((x) >> 3) & 0x70))

__device__ __forceinline__ void store_split(__half* p, float v) {
    __half hi = __float2half_rn(v);
    p[0]   = hi;
    p[256] = __float2half_rn(v - __half2float(hi));
}

// ============================================================================
// prep_a: embed+proj | transpose W_hh | reset sync   (feeds rnn, stream 0)
// ============================================================================
#define NB_EMB 400
#define NB_TRA 256
#define NB_PREPA (NB_EMB + NB_TRA)
#define NB_PREPB (NPAD / 4)        // 2528 blocks: W_aff -> fp16

__global__ void __launch_bounds__(256)
prep_a(const int* __restrict__ xraw,
       const float* __restrict__ emb,
       const float* __restrict__ W_ih,
       const float* __restrict__ b_ih,
       const float* __restrict__ b_hh,
       const float* __restrict__ W_hh)
{
    const int bb = blockIdx.x;

    if (bb >= NB_EMB) {                          // ---- transpose W_hh ----
        int idx = (bb - NB_EMB) * 256 + threadIdx.x;  // 65536 elems
        int k = idx >> 8, j = idx & 255;
        g_WT[k * HH + j] = W_hh[j * HH + k];
        return;
    }

    // ---- embedding + input projection (16 rows per block) ----
    if (bb == 0 && threadIdx.x < SS) g_prog[threadIdx.x] = 0;   // reset progress
    if (bb == 0 && threadIdx.x == 255) g_ticket = 0;            // reset tickets

    __shared__ __align__(16) float se[16][XX];

    const bool is64 = ((xraw[1] | xraw[3] | xraw[5] | xraw[7] | xraw[9]) == 0) &&
                      ((xraw[0] | xraw[2] | xraw[4] | xraw[6] | xraw[8]) != 0);

    const int m0 = bb * 16;
    for (int i = threadIdx.x; i < 16 * (XX / 4); i += 256) {
        int r = i >> 5, c = i & 31;
        int m = m0 + r;
        int tok = is64 ? xraw[2 * m] : xraw[m];
        ((float4*)se[r])[c] = ((const float4*)(emb + (long long)tok * XX))[c];
    }
    __syncthreads();

    const int j = threadIdx.x;
    const float bias = b_ih[j] + b_hh[j];
    float acc[16];
#pragma unroll
    for (int r = 0; r < 16; r++) acc[r] = bias;

    const float* wr = W_ih + j * XX;
#pragma unroll 4
    for (int k = 0; k < XX; k += 4) {
        float4 w = *(const float4*)(wr + k);
#pragma unroll
        for (int r = 0; r < 16; r++) {
            float4 e = *(const float4*)&se[r][k];
            acc[r] = fmaf(w.x, e.x, fmaf(w.y, e.y, fmaf(w.z, e.z, fmaf(w.w, e.w, acc[r]))));
        }
    }
#pragma unroll
    for (int r = 0; r < 16; r++)
        g_xin[(m0 + r) * HH + j] = acc[r];
}

// ============================================================================
// prep_b: W_aff -> fp16  (feeds consumers, stream s2, concurrent with prep_a)
// ============================================================================
__global__ void __launch_bounds__(256)
prep_b(const float* __restrict__ Wa)
{
    int idx = blockIdx.x * 256 + threadIdx.x;   // NPAD * 64
    int n  = idx >> 6;
    int k4 = (idx & 63) << 2;
    float4 w = make_float4(0.f, 0.f, 0.f, 0.f);
    if (n < VV) w = *(const float4*)(Wa + (size_t)n * 256 + k4);
    __half* p = g_B2 + (size_t)n * 256 + k4;
    p[0] = __float2half_rn(w.x);
    p[1] = __float2half_rn(w.y);
    p[2] = __float2half_rn(w.z);
    p[3] = __float2half_rn(w.w);
}

// ============================================================================
// Persistent GEMM consumer loop.
//   C[m][n] = A_hi.B + A_lo.B + bias   (fp16 x fp16 -> fp32, K_eff = 512)
// ============================================================================
#define RNN_W_F2   (128 * 64)            // float2: quarter of W
#define HB_STRIDE  258                   // padded rq stride (bank-disjoint)
#define RNN_HB_F2  (2 * 4 * HB_STRIDE)
#define TILE_BYTES 16384
#define STAGE_BYTES (2 * TILE_BYTES)
#define NSTAGE 3
#define SMEM_TILES (NSTAGE * STAGE_BYTES)   // 98304 (rnn scan uses ~82 KB subset)
#define NB_RNN 64
#define NB_GEMM 232
#define NCHUNK 8

__device__ void consume_tiles(const float* __restrict__ ba, float* __restrict__ C,
                              char* smem, int tid)
{
    const uint32_t sb = smem_u32(smem);
    const int wid  = tid >> 5;
    const int lane = tid & 31;

    uint32_t t_sw[4];
    int l_row[4], l_c[4];
#pragma unroll
    for (int i = 0; i < 4; i++) {
        int idx = i * 256 + tid;
        l_row[i] = idx >> 3; l_c[i] = idx & 7;
        t_sw[i] = SW128(l_row[i] * 128 + l_c[i] * 16);
    }

    const int wm0 = (wid >> 1) * 32;
    const int wn0 = (wid & 1) * 64;
    const int a_row  = wm0 + (lane & 7) + ((lane & 8) ? 8 : 0);
    const int a_koff = (lane & 16) ? 16 : 0;
    const int b_row  = wn0 + (lane & 7) + ((lane & 16) ? 8 : 0);
    const int b_koff = (lane & 8) ? 16 : 0;
    const int lm = lane >> 2;
    const int lq = (lane & 3) * 2;

    __shared__ int s_ticket;

    for (;;) {
        if (tid == 0) s_ticket = atomicAdd(&g_ticket, 1);
        __syncthreads();
        const int ticket = s_ticket;
        __syncthreads();
        if (ticket >= N_TICKETS) return;

        const int tT = ticket / NT_N;
        const int bn = (ticket % NT_N) * 128;
        const int bm = tT * 128;

        if (tid == 0) {
            while (ld_acq(&g_prog[tT]) < NB_RNN) __nanosleep(128);
        }
        __syncthreads();

        const __half* a_src[4];
        const __half* b_src[4];
#pragma unroll
        for (int i = 0; i < 4; i++) {
            a_src[i] = g_A2 + (size_t)(bm + l_row[i]) * 512 + l_c[i] * 8;
            b_src[i] = g_B2 + (size_t)(bn + l_row[i]) * 256 + l_c[i] * 8;
        }

        float acc[2][8][4];
#pragma unroll
        for (int mt = 0; mt < 2; mt++)
#pragma unroll
            for (int nt = 0; nt < 8; nt++)
#pragma unroll
                for (int q = 0; q < 4; q++) acc[mt][nt][q] = 0.f;

        // chunks: seg = ch>>2 (0: A_hi, 1: A_lo), s = ch&3 (k quarter)
        auto prefetch = [&](int ch) {
            const int seg = ch >> 2, s = ch & 3;
            const int aoff = seg * 256 + s * 64;
            const int boff = s * 64;
            const uint32_t base = sb + (ch % NSTAGE) * STAGE_BYTES;
#pragma unroll
            for (int i = 0; i < 4; i++) cp_async16(base + t_sw[i], a_src[i] + aoff);
#pragma unroll
            for (int i = 0; i < 4; i++) cp_async16(base + TILE_BYTES + t_sw[i], b_src[i] + boff);
            asm volatile("cp.async.commit_group;" ::: "memory");
        };

        prefetch(0);
        prefetch(1);

#pragma unroll 1
        for (int ch = 0; ch < NCHUNK; ++ch) {
            if (ch < NCHUNK - 1) asm volatile("cp.async.wait_group 1;" ::: "memory");
            else                 asm volatile("cp.async.wait_group 0;" ::: "memory");
            __syncthreads();
            if (ch + 2 < NCHUNK) prefetch(ch + 2);

            const uint32_t Ab = sb + (ch % NSTAGE) * STAGE_BYTES;
            const uint32_t Bb = Ab + TILE_BYTES;

#pragma unroll
            for (int ks = 0; ks < 4; ++ks) {
                const int kb = ks * 32;
                uint32_t a[2][4], b[4][4];
#pragma unroll
                for (int mt = 0; mt < 2; mt++)
                    ldsm4(a[mt], Ab + SW128((a_row + mt * 16) * 128 + kb + a_koff));
#pragma unroll
                for (int p = 0; p < 4; p++)
                    ldsm4(b[p], Bb + SW128((b_row + p * 16) * 128 + kb + b_koff));
#pragma unroll
                for (int mt = 0; mt < 2; mt++)
#pragma unroll
                    for (int p = 0; p < 4; p++) {
                        mma16816(acc[mt][2 * p + 0], a[mt], b[p][0], b[p][1]);
                        mma16816(acc[mt][2 * p + 1], a[mt], b[p][2], b[p][3]);
                    }
            }
        }

        // epilogue: C row for tile-local row b is m_orig = b*SS + tT
#pragma unroll
        for (int nt = 0; nt < 8; nt++) {
            const int gcol = bn + wn0 + nt * 8 + lq;
            if (gcol >= VV) continue;
            const float2 bv = *(const float2*)(ba + gcol);
#pragma unroll
            for (int mt = 0; mt < 2; mt++) {
                const int brow = wm0 + mt * 16 + lm;             // batch index
                float* c0 = C + ((size_t)brow * SS + tT) * VV + gcol;
                float2 o0 = make_float2(acc[mt][nt][0] + bv.x, acc[mt][nt][1] + bv.y);
                float2 o1 = make_float2(acc[mt][nt][2] + bv.x, acc[mt][nt][3] + bv.y);
                *(float2*)c0                         = o0;
                *(float2*)(c0 + (size_t)8 * SS * VV) = o1;       // brow+8
            }
        }
        __syncthreads();
    }
}

// ============================================================================
// RNN kernel (cluster-4, 64 CTAs). Lane remap rq=tid&3, jl=tid>>2 so each warp
// holds 8 jl x 4 rq: W reads collapse to 64B/warp (4-way broadcast) and the 4
// rq h-reads hit distinct banks (HB_STRIDE pad). After the scan -> consumer.
// ============================================================================
__global__ void __launch_bounds__(256, 2) __cluster_dims__(4, 1, 1)
rnn_then_consume(const float* __restrict__ ba, float* __restrict__ C)
{
    extern __shared__ __align__(1024) char smem[];
    const int bid = blockIdx.x;
    const int tid = threadIdx.x;

    {
        float2* wsp = (float2*)smem;            // [k2*64 + jl], k2=0..127
        float2* hb  = (float2*)smem + RNN_W_F2; // [(buf*4 + rq)*HB_STRIDE + col]
        const uint32_t hb_addr = smem_u32(hb);

        const int rq   = tid & 3;               // rowpair 0..3   (remapped)
        const int jl   = tid >> 2;               // column  0..63  (remapped)
        const uint32_t rank = bid & 3;
        const int jg   = rank * 64 + jl;        // global output column
        const int b0   = (bid >> 2) * 8;        // 8 batch rows per cluster

        for (int i = tid; i < RNN_W_F2; i += 256) {
            int k2 = i >> 6, j = i & 63;
            int jgl = rank * 64 + j;
            wsp[i] = make_float2(g_WT[(2 * k2) * HH + jgl],
                                 g_WT[(2 * k2 + 1) * HH + jgl]);
        }
        for (int i = tid; i < RNN_HB_F2; i += 256) hb[i] = make_float2(0.f, 0.f);

        asm volatile("barrier.cluster.arrive.aligned;" ::: "memory");
        asm volatile("barrier.cluster.wait.aligned;" ::: "memory");

        const int r0 = b0 + 2 * rq;
        const float* x0p = g_xin + (size_t)r0 * SS * HH + jg;
        const float* x1p = g_xin + (size_t)(r0 + 1) * SS * HH + jg;
        __half* a0p = g_A2 + (size_t)r0 * 512 + jg;        // + t*BB*512
        __half* a1p = g_A2 + (size_t)(r0 + 1) * 512 + jg;

        const float2* wp = wsp + jl;
        const uint32_t p1 = rank ^ 1, p2 = rank ^ 2, p3 = rank ^ 3;

        float xa = x0p[0], xb = x1p[0];
        int cur = 0;
        for (int t = 0; t < SS; ++t) {
            double acc_e = pk2(xa, xb);
            double acc_o = 0.0;
            if (t + 1 < SS) {
                xa = x0p[(size_t)(t + 1) * HH];
                xb = x1p[(size_t)(t + 1) * HH];
            }

            const double2* hc = (const double2*)(hb + (cur * 4 + rq) * HB_STRIDE);
#pragma unroll 8
            for (int k2 = 0; k2 < 128; ++k2) {
                float2 wv  = wp[k2 * 64];
                double2 h2 = hc[k2];
                ffma2(acc_e, dup2(wv.x), h2.x);
                ffma2(acc_o, dup2(wv.y), h2.y);
            }

            float2 f = unpk(fadd2(acc_e, acc_o));
            float h0 = tanhf(f.x), h1 = tanhf(f.y);

            const int nxt = cur ^ 1;
            const long long hp = __double_as_longlong(pk2(h0, h1));
            uint32_t loc = hb_addr + (uint32_t)(((nxt * 4 + rq) * HB_STRIDE + jg) * 8);
            asm volatile("st.shared.b64 [%0], %1;" :: "r"(loc), "l"(hp) : "memory");
            asm volatile(
                "{\n\t.reg .b32 ra;\n\t"
                "mapa.shared::cluster.u32 ra, %0, %1;\n\t"
                "st.shared::cluster.b64 [ra], %2;\n\t"
                "mapa.shared::cluster.u32 ra, %0, %3;\n\t"
                "st.shared::cluster.b64 [ra], %2;\n\t"
                "mapa.shared::cluster.u32 ra, %0, %4;\n\t"
                "st.shared::cluster.b64 [ra], %2;\n\t}"
                :: "r"(loc), "r"(p1), "l"(hp), "r"(p2), "r"(p3) : "memory");

            store_split(a0p + (size_t)t * (BB * 512), h0);
            store_split(a1p + (size_t)t * (BB * 512), h1);

            asm volatile("barrier.cluster.arrive.aligned;" ::: "memory");
            asm volatile("barrier.cluster.wait.aligned;" ::: "memory");
            if (tid == 0) red_release(&g_prog[t]);
            cur = nxt;
        }
    }
    __syncthreads();
    // Scan done: convert this CTA into a gemm consumer (reuses smem).
    consume_tiles(ba, C, smem, tid);
}

// ============================================================================
// Pure consumer kernel (no cluster -> full scheduling flexibility)
// ============================================================================
__global__ void __launch_bounds__(256, 2)
gemm_consume(const float* __restrict__ ba, float* __restrict__ C)
{
    extern __shared__ __align__(1024) char smem[];
    consume_tiles(ba, C, smem, threadIdx.x);
}

// ============================================================================
extern "C" void kernel_launch(void* const* d_in, const int* in_sizes, int n_in,
                              void* d_out, int out_size)
{
    const int*   x     = (const int*)  d_in[0];
    const float* emb   = (const float*)d_in[1];
    const float* W_ih  = (const float*)d_in[2];
    const float* W_hh  = (const float*)d_in[3];
    const float* b_ih  = (const float*)d_in[4];
    const float* b_hh  = (const float*)d_in[5];
    const float* W_aff = (const float*)d_in[6];
    const float* b_aff = (const float*)d_in[7];
    float* out = (float*)d_out;

    static cudaStream_t s2 = nullptr;
    static cudaEvent_t evF = nullptr, evA = nullptr, evB = nullptr;
    if (s2 == nullptr) {
        cudaStreamCreateWithFlags(&s2, cudaStreamNonBlocking);
        cudaEventCreateWithFlags(&evF, cudaEventDisableTiming);
        cudaEventCreateWithFlags(&evA, cudaEventDisableTiming);
        cudaEventCreateWithFlags(&evB, cudaEventDisableTiming);
        cudaFuncSetAttribute(rnn_then_consume,
                             cudaFuncAttributeMaxDynamicSharedMemorySize, SMEM_TILES);
        cudaFuncSetAttribute(gemm_consume,
                             cudaFuncAttributeMaxDynamicSharedMemorySize, SMEM_TILES);
    }

    // fork s2 off the capture stream
    cudaEventRecord(evF, 0);
    cudaStreamWaitEvent(s2, evF, 0);

    prep_a<<<NB_PREPA, 256>>>(x, emb, W_ih, b_ih, b_hh, W_hh);   // stream 0
    prep_b<<<NB_PREPB, 256, 0, s2>>>(W_aff);                     // stream s2 (concurrent)

    cudaEventRecord(evA, 0);                 // prep_a (incl. sync resets) done
    cudaStreamWaitEvent(s2, evA, 0);         // consumers need resets + will spin on g_prog

    rnn_then_consume<<<NB_RNN, 256, SMEM_TILES>>>(b_aff, out);          // stream 0
    gemm_consume<<<NB_GEMM, 256, SMEM_TILES, s2>>>(b_aff, out);         // stream s2

    // join
    cudaEventRecord(evB, s2);
    cudaStreamWaitEvent(0, evB, 0);
}

// round 14
// speedup vs baseline: 1.0930x; 1.0930x over previous
#include <cuda_runtime.h>
#include <cuda_fp16.h>
#include <cstdint>

#define BB 128
#define SS 50
#define XX 128
#define HH 256
#define VV 10000
#define MM (BB*SS)     // 6400
#define NT_N 79
#define NPAD (NT_N * 128)   // 10112
#define N_TICKETS (SS * NT_N)

// ---------------- device scratch (no allocs allowed in kernel_launch) ------
__device__ float g_xin[MM * HH];                         // input projection [b][t][j]
__device__ float g_WT[HH * HH];                          // W_hh transposed: [k][j]
// t-MAJOR: row m = t*128 + b ; [m][0:256]=hi, [256:512]=lo  (fp16 split of h)
__device__ __align__(16) __half g_A2[MM * 512];
__device__ __align__(16) __half g_B2[(size_t)NPAD * 256];   // W_aff in plain fp16
__device__ int g_prog[SS];                               // per-step producer arrivals
__device__ int g_ticket;                                 // persistent consumer tickets

// ---------------- packed fp32x2 helpers --------------------------------------
__device__ __forceinline__ double dup2(float x) {
    double r; asm("mov.b64 %0, {%1, %1};" : "=d"(r) : "f"(x)); return r;
}
__device__ __forceinline__ double pk2(float lo, float hi) {
    double r; asm("mov.b64 %0, {%1, %2};" : "=d"(r) : "f"(lo), "f"(hi)); return r;
}
__device__ __forceinline__ float2 unpk(double d) {
    float2 f; asm("mov.b64 {%0, %1}, %2;" : "=f"(f.x), "=f"(f.y) : "d"(d)); return f;
}
__device__ __forceinline__ void ffma2(double& acc, double a, double b) {
    asm("fma.rn.f32x2 %0, %1, %2, %0;" : "+d"(acc) : "d"(a), "d"(b));
}
__device__ __forceinline__ double fadd2(double a, double b) {
    double r; asm("add.rn.f32x2 %0, %1, %2;" : "=d"(r) : "d"(a), "d"(b)); return r;
}

// ---------------- mma / smem helpers ------------------------------------------
__device__ __forceinline__ uint32_t smem_u32(const void* p) {
    uint32_t a;
    asm("{ .reg .u64 t; cvta.to.shared.u64 t, %1; cvt.u32.u64 %0, t; }" : "=r"(a) : "l"(p));
    return a;
}
__device__ __forceinline__ void cp_async16(uint32_t dst, const void* src) {
    asm volatile("cp.async.cg.shared.global [%0], [%1], 16;"
                 :: "r"(dst), "l"(src) : "memory");
}
__device__ __forceinline__ void ldsm4(uint32_t r[4], uint32_t addr) {
    asm volatile("ldmatrix.sync.aligned.m8n8.x4.shared.b16 {%0,%1,%2,%3}, [%4];"
                 : "=r"(r[0]), "=r"(r[1]), "=r"(r[2]), "=r"(r[3]) : "r"(addr));
}
__device__ __forceinline__ void mma16816(float c[4], const uint32_t a[4],
                                         uint32_t b0, uint32_t b1) {
    asm volatile(
        "mma.sync.aligned.m16n8k16.row.col.f32.f16.f16.f32 "
        "{%0,%1,%2,%3}, {%4,%5,%6,%7}, {%8,%9}, {%0,%1,%2,%3};"
        : "+f"(c[0]), "+f"(c[1]), "+f"(c[2]), "+f"(c[3])
        : "r"(a[0]), "r"(a[1]), "r"(a[2]), "r"(a[3]), "r"(b0), "r"(b1));
}
__device__ __forceinline__ int ld_acq(const int* p) {
    int v; asm volatile("ld.acquire.gpu.global.b32 %0, [%1];" : "=r"(v) : "l"(p)); return v;
}
__device__ __forceinline__ void red_release(int* p) {
    asm volatile("red.release.gpu.global.add.s32 [%0], %1;" :: "l"(p), "r"(1) : "memory");
}
#define SW128(x) ((x) ^ (((x) >> 3) & 0x70))

__device__ __forceinline__ void store_split(__half* p, float v) {
    __half hi = __float2half_rn(v);
    p[0]   = hi;
    p[256] = __float2half_rn(v - __half2float(hi));
}

// ============================================================================
// Kernel A (fused prep): embed+proj | fp16 W_aff | transpose W_hh | reset sync
// ============================================================================
#define NB_EMB 400
#define NB_SPL (NPAD / 4)        // 2528
#define NB_TRA 256
#define NB_PREP (NB_EMB + NB_SPL + NB_TRA)

__global__ void __launch_bounds__(256)
prep(const int* __restrict__ xraw,
     const float* __restrict__ emb,
     const float* __restrict__ W_ih,
     const float* __restrict__ b_ih,
     const float* __restrict__ b_hh,
     const float* __restrict__ W_hh,
     const float* __restrict__ Wa)
{
    const int bb = blockIdx.x;

    if (bb >= NB_EMB + NB_SPL) {                 // ---- transpose W_hh ----
        int idx = (bb - NB_EMB - NB_SPL) * 256 + threadIdx.x;  // 65536 elems
        int k = idx >> 8, j = idx & 255;
        g_WT[k * HH + j] = W_hh[j * HH + k];
        return;
    }
    if (bb >= NB_EMB) {                          // ---- W_aff -> fp16 ----
        int idx = (bb - NB_EMB) * 256 + threadIdx.x;   // NPAD * 64
        int n  = idx >> 6;
        int k4 = (idx & 63) << 2;
        float4 w = make_float4(0.f, 0.f, 0.f, 0.f);
        if (n < VV) w = *(const float4*)(Wa + (size_t)n * 256 + k4);
        __half* p = g_B2 + (size_t)n * 256 + k4;
        p[0] = __float2half_rn(w.x);
        p[1] = __float2half_rn(w.y);
        p[2] = __float2half_rn(w.z);
        p[3] = __float2half_rn(w.w);
        return;
    }

    // ---- embedding + input projection (16 rows per block) ----
    if (bb == 0 && threadIdx.x < SS) g_prog[threadIdx.x] = 0;   // reset progress
    if (bb == 0 && threadIdx.x == 255) g_ticket = 0;            // reset tickets

    __shared__ __align__(16) float se[16][XX];

    const bool is64 = ((xraw[1] | xraw[3] | xraw[5] | xraw[7] | xraw[9]) == 0) &&
                      ((xraw[0] | xraw[2] | xraw[4] | xraw[6] | xraw[8]) != 0);

    const int m0 = bb * 16;
    for (int i = threadIdx.x; i < 16 * (XX / 4); i += 256) {
        int r = i >> 5, c = i & 31;
        int m = m0 + r;
        int tok = is64 ? xraw[2 * m] : xraw[m];
        ((float4*)se[r])[c] = ((const float4*)(emb + (long long)tok * XX))[c];
    }
    __syncthreads();

    const int j = threadIdx.x;
    const float bias = b_ih[j] + b_hh[j];
    float acc[16];
#pragma unroll
    for (int r = 0; r < 16; r++) acc[r] = bias;

    const float* wr = W_ih + j * XX;
#pragma unroll 4
    for (int k = 0; k < XX; k += 4) {
        float4 w = *(const float4*)(wr + k);
#pragma unroll
        for (int r = 0; r < 16; r++) {
            float4 e = *(const float4*)&se[r][k];
            acc[r] = fmaf(w.x, e.x, fmaf(w.y, e.y, fmaf(w.z, e.z, fmaf(w.w, e.w, acc[r]))));
        }
    }
#pragma unroll
    for (int r = 0; r < 16; r++)
        g_xin[(m0 + r) * HH + j] = acc[r];
}

// ============================================================================
// Persistent GEMM consumer loop.
//   C[m][n] = A_hi.B + A_lo.B + bias   (fp16 x fp16 -> fp32, K_eff = 512)
//   Chunk order ch = 2*s + seg (s = k-quarter, seg = hi/lo): B(s) is shared by
//   the chunk pair -> B loaded once per s into a 2-deep ring (A ring 3-deep).
// ============================================================================
#define RNN_W_F2   (128 * 64)            // float2: quarter of W
#define RNN_HB_F2  (2 * 4 * 256)         // [buf][rq][col]
#define A_TILE 16384
#define NSTAGE_A 3
#define NSTAGE_B 2
#define SMEM_TILES ((NSTAGE_A + NSTAGE_B) * A_TILE)   // 81920 == rnn's 80 KB
#define NB_RNN 64
#define NB_GEMM 232
#define NCHUNK 8

__device__ void consume_tiles(const float* __restrict__ ba, float* __restrict__ C,
                              char* smem, int tid)
{
    const uint32_t sb  = smem_u32(smem);
    const uint32_t sbB = sb + NSTAGE_A * A_TILE;
    const int wid  = tid >> 5;
    const int lane = tid & 31;

    uint32_t t_sw[4];
    int l_row[4], l_c[4];
#pragma unroll
    for (int i = 0; i < 4; i++) {
        int idx = i * 256 + tid;
        l_row[i] = idx >> 3; l_c[i] = idx & 7;
        t_sw[i] = SW128(l_row[i] * 128 + l_c[i] * 16);
    }

    const int wm0 = (wid >> 1) * 32;
    const int wn0 = (wid & 1) * 64;
    const int a_row  = wm0 + (lane & 7) + ((lane & 8) ? 8 : 0);
    const int a_koff = (lane & 16) ? 16 : 0;
    const int b_row  = wn0 + (lane & 7) + ((lane & 16) ? 8 : 0);
    const int b_koff = (lane & 8) ? 16 : 0;
    const int lm = lane >> 2;
    const int lq = (lane & 3) * 2;

    __shared__ int s_ticket;

    for (;;) {
        if (tid == 0) s_ticket = atomicAdd(&g_ticket, 1);
        __syncthreads();
        const int ticket = s_ticket;
        __syncthreads();
        if (ticket >= N_TICKETS) return;

        const int tT = ticket / NT_N;
        const int bn = (ticket % NT_N) * 128;
        const int bm = tT * 128;

        if (tid == 0) {
            while (ld_acq(&g_prog[tT]) < NB_RNN) __nanosleep(128);
        }
        __syncthreads();

        const __half* a_src[4];
        const __half* b_src[4];
#pragma unroll
        for (int i = 0; i < 4; i++) {
            a_src[i] = g_A2 + (size_t)(bm + l_row[i]) * 512 + l_c[i] * 8;
            b_src[i] = g_B2 + (size_t)(bn + l_row[i]) * 256 + l_c[i] * 8;
        }

        float acc[2][8][4];
#pragma unroll
        for (int mt = 0; mt < 2; mt++)
#pragma unroll
            for (int nt = 0; nt < 8; nt++)
#pragma unroll
                for (int q = 0; q < 4; q++) acc[mt][nt][q] = 0.f;

        // ch = 2*s + seg: s = ch>>1 (k-quarter), seg = ch&1 (A hi/lo).
        // A -> ring ch%3; B(s) loaded on even ch -> ring (ch>>1)&1.
        auto prefetch = [&](int ch) {
            const int s = ch >> 1, seg = ch & 1;
            const int aoff = seg * 256 + s * 64;
            const uint32_t abase = sb + (ch % NSTAGE_A) * A_TILE;
#pragma unroll
            for (int i = 0; i < 4; i++) cp_async16(abase + t_sw[i], a_src[i] + aoff);
            if (!seg) {
                const uint32_t bbase = sbB + (s & 1) * A_TILE;
#pragma unroll
                for (int i = 0; i < 4; i++) cp_async16(bbase + t_sw[i], b_src[i] + s * 64);
            }
            asm volatile("cp.async.commit_group;" ::: "memory");
        };

        prefetch(0);
        prefetch(1);

#pragma unroll 1
        for (int ch = 0; ch < NCHUNK; ++ch) {
            if (ch < NCHUNK - 1) asm volatile("cp.async.wait_group 1;" ::: "memory");
            else                 asm volatile("cp.async.wait_group 0;" ::: "memory");
            __syncthreads();
            if (ch + 2 < NCHUNK) prefetch(ch + 2);

            const uint32_t Ab = sb  + (ch % NSTAGE_A) * A_TILE;
            const uint32_t Bb = sbB + ((ch >> 1) & 1) * A_TILE;

#pragma unroll
            for (int ks = 0; ks < 4; ++ks) {
                const int kb = ks * 32;
                uint32_t a[2][4], b[4][4];
#pragma unroll
                for (int mt = 0; mt < 2; mt++)
                    ldsm4(a[mt], Ab + SW128((a_row + mt * 16) * 128 + kb + a_koff));
#pragma unroll
                for (int p = 0; p < 4; p++)
                    ldsm4(b[p], Bb + SW128((b_row + p * 16) * 128 + kb + b_koff));
#pragma unroll
                for (int mt = 0; mt < 2; mt++)
#pragma unroll
                    for (int p = 0; p < 4; p++) {
                        mma16816(acc[mt][2 * p + 0], a[mt], b[p][0], b[p][1]);
                        mma16816(acc[mt][2 * p + 1], a[mt], b[p][2], b[p][3]);
                    }
            }
        }

        // epilogue: C row for tile-local row b is m_orig = b*SS + tT
#pragma unroll
        for (int nt = 0; nt < 8; nt++) {
            const int gcol = bn + wn0 + nt * 8 + lq;
            if (gcol >= VV) continue;
            const float2 bv = *(const float2*)(ba + gcol);
#pragma unroll
            for (int mt = 0; mt < 2; mt++) {
                const int brow = wm0 + mt * 16 + lm;             // batch index
                float* c0 = C + ((size_t)brow * SS + tT) * VV + gcol;
                float2 o0 = make_float2(acc[mt][nt][0] + bv.x, acc[mt][nt][1] + bv.y);
                float2 o1 = make_float2(acc[mt][nt][2] + bv.x, acc[mt][nt][3] + bv.y);
                *(float2*)c0                         = o0;
                *(float2*)(c0 + (size_t)8 * SS * VV) = o1;       // brow+8
            }
        }
        __syncthreads();
    }
}

// ============================================================================
// RNN kernel (cluster-4, 64 CTAs), R12 lane mapping (rq=tid>>6, jl=tid&63).
// After the scan, CTAs become gemm consumers.
// ============================================================================
__global__ void __launch_bounds__(256, 2) __cluster_dims__(4, 1, 1)
rnn_then_consume(const float* __restrict__ ba, float* __restrict__ C)
{
    extern __shared__ __align__(1024) char smem[];
    const int bid = blockIdx.x;
    const int tid = threadIdx.x;

    {
        float2* wsp = (float2*)smem;            // [k2*64 + jl], k2=0..127
        float2* hb  = (float2*)smem + RNN_W_F2; // [(buf*4 + rq)*256 + col]
        const uint32_t hb_addr = smem_u32(hb);

        const int rq   = tid >> 6;              // rowpair 0..3
        const int jl   = tid & 63;
        const uint32_t rank = bid & 3;
        const int jg   = rank * 64 + jl;        // global output column
        const int b0   = (bid >> 2) * 8;        // 8 batch rows per cluster

        for (int i = tid; i < RNN_W_F2; i += 256) {
            int k2 = i >> 6, j = i & 63;
            int jgl = rank * 64 + j;
            wsp[i] = make_float2(g_WT[(2 * k2) * HH + jgl],
                                 g_WT[(2 * k2 + 1) * HH + jgl]);
        }
        for (int i = tid; i < 4 * 256; i += 256) hb[i] = make_float2(0.f, 0.f);

        asm volatile("barrier.cluster.arrive.aligned;" ::: "memory");
        asm volatile("barrier.cluster.wait.aligned;" ::: "memory");

        const int r0 = b0 + 2 * rq;
        const float* x0p = g_xin + (size_t)r0 * SS * HH + jg;
        const float* x1p = g_xin + (size_t)(r0 + 1) * SS * HH + jg;
        __half* a0p = g_A2 + (size_t)r0 * 512 + jg;        // + t*BB*512
        __half* a1p = g_A2 + (size_t)(r0 + 1) * 512 + jg;

        const float2* wp = wsp + jl;
        const uint32_t p1 = rank ^ 1, p2 = rank ^ 2, p3 = rank ^ 3;

        float xa = x0p[0], xb = x1p[0];
        int cur = 0;
        for (int t = 0; t < SS; ++t) {
            double acc_e = pk2(xa, xb);
            double acc_o = 0.0;
            if (t + 1 < SS) {
                xa = x0p[(size_t)(t + 1) * HH];
                xb = x1p[(size_t)(t + 1) * HH];
            }

            const double2* hc = (const double2*)(hb + (cur * 4 + rq) * 256);
#pragma unroll 8
            for (int k2 = 0; k2 < 128; ++k2) {
                float2 wv  = wp[k2 * 64];
                double2 h2 = hc[k2];
                ffma2(acc_e, dup2(wv.x), h2.x);
                ffma2(acc_o, dup2(wv.y), h2.y);
            }

            float2 f = unpk(fadd2(acc_e, acc_o));
            float h0 = tanhf(f.x), h1 = tanhf(f.y);

            const int nxt = cur ^ 1;
            const long long hp = __double_as_longlong(pk2(h0, h1));
            uint32_t loc = hb_addr + (uint32_t)(((nxt * 4 + rq) * 256 + jg) * 8);
            asm volatile("st.shared.b64 [%0], %1;" :: "r"(loc), "l"(hp) : "memory");
            asm volatile(
                "{\n\t.reg .b32 ra;\n\t"
                "mapa.shared::cluster.u32 ra, %0, %1;\n\t"
                "st.shared::cluster.b64 [ra], %2;\n\t"
                "mapa.shared::cluster.u32 ra, %0, %3;\n\t"
                "st.shared::cluster.b64 [ra], %2;\n\t"
                "mapa.shared::cluster.u32 ra, %0, %4;\n\t"
                "st.shared::cluster.b64 [ra], %2;\n\t}"
                :: "r"(loc), "r"(p1), "l"(hp), "r"(p2), "r"(p3) : "memory");

            store_split(a0p + (size_t)t * (BB * 512), h0);
            store_split(a1p + (size_t)t * (BB * 512), h1);

            asm volatile("barrier.cluster.arrive.aligned;" ::: "memory");
            asm volatile("barrier.cluster.wait.aligned;" ::: "memory");
            if (tid == 0) red_release(&g_prog[t]);
            cur = nxt;
        }
    }
    __syncthreads();
    // Scan done: convert this CTA into a gemm consumer (reuses smem).
    consume_tiles(ba, C, smem, tid);
}

// ============================================================================
// Pure consumer kernel (no cluster -> full scheduling flexibility)
// ============================================================================
__global__ void __launch_bounds__(256, 2)
gemm_consume(const float* __restrict__ ba, float* __restrict__ C)
{
    extern __shared__ __align__(1024) char smem[];
    consume_tiles(ba, C, smem, threadIdx.x);
}

// ============================================================================
extern "C" void kernel_launch(void* const* d_in, const int* in_sizes, int n_in,
                              void* d_out, int out_size)
{
    const int*   x     = (const int*)  d_in[0];
    const float* emb   = (const float*)d_in[1];
    const float* W_ih  = (const float*)d_in[2];
    const float* W_hh  = (const float*)d_in[3];
    const float* b_ih  = (const float*)d_in[4];
    const float* b_hh  = (const float*)d_in[5];
    const float* W_aff = (const float*)d_in[6];
    const float* b_aff = (const float*)d_in[7];
    float* out = (float*)d_out;

    static cudaStream_t s2 = nullptr;
    static cudaEvent_t evA = nullptr, evB = nullptr;
    if (s2 == nullptr) {
        cudaStreamCreateWithFlags(&s2, cudaStreamNonBlocking);
        cudaEventCreateWithFlags(&evA, cudaEventDisableTiming);
        cudaEventCreateWithFlags(&evB, cudaEventDisableTiming);
        cudaFuncSetAttribute(rnn_then_consume,
                             cudaFuncAttributeMaxDynamicSharedMemorySize, SMEM_TILES);
        cudaFuncSetAttribute(gemm_consume,
                             cudaFuncAttributeMaxDynamicSharedMemorySize, SMEM_TILES);
    }

    prep<<<NB_PREP, 256>>>(x, emb, W_ih, b_ih, b_hh, W_hh, W_aff);

    // fork: consumers run concurrently with the rnn producer kernel
    cudaEventRecord(evA, 0);
    cudaStreamWaitEvent(s2, evA, 0);

    rnn_then_consume<<<NB_RNN, 256, SMEM_TILES>>>(b_aff, out);          // stream 0
    gemm_consume<<<NB_GEMM, 256, SMEM_TILES, s2>>>(b_aff, out);         // stream s2

    // join
    cudaEventRecord(evB, s2);
    cudaStreamWaitEvent(0, evB, 0);
}

// round 15
// speedup vs baseline: 1.0937x; 1.0007x over previous
#include <cuda_runtime.h>
#include <cuda_fp16.h>
#include <cstdint>

#define BB 128
#define SS 50
#define XX 128
#define HH 256
#define VV 10000
#define MM (BB*SS)     // 6400
#define NT_N 79
#define NPAD (NT_N * 128)   // 10112
#define N_TICKETS (SS * NT_N)

// ---------------- device scratch (no allocs allowed in kernel_launch) ------
__device__ float g_xin[MM * HH];                         // input projection [b][t][j]
__device__ float g_WT[HH * HH];                          // W_hh transposed: [k][j]
// t-MAJOR: row m = t*128 + b ; [m][0:256]=hi, [256:512]=lo  (fp16 split of h)
__device__ __align__(16) __half g_A2[MM * 512];
__device__ __align__(16) __half g_B2[(size_t)NPAD * 256];   // W_aff in plain fp16
__device__ int g_prog[SS];                               // per-step producer arrivals
__device__ int g_ticket;                                 // persistent consumer tickets

// ---------------- packed fp32x2 helpers --------------------------------------
__device__ __forceinline__ double dup2(float x) {
    double r; asm("mov.b64 %0, {%1, %1};" : "=d"(r) : "f"(x)); return r;
}
__device__ __forceinline__ double pk2(float lo, float hi) {
    double r; asm("mov.b64 %0, {%1, %2};" : "=d"(r) : "f"(lo), "f"(hi)); return r;
}
__device__ __forceinline__ float2 unpk(double d) {
    float2 f; asm("mov.b64 {%0, %1}, %2;" : "=f"(f.x), "=f"(f.y) : "d"(d)); return f;
}
__device__ __forceinline__ void ffma2(double& acc, double a, double b) {
    asm("fma.rn.f32x2 %0, %1, %2, %0;" : "+d"(acc) : "d"(a), "d"(b));
}
__device__ __forceinline__ double fadd2(double a, double b) {
    double r; asm("add.rn.f32x2 %0, %1, %2;" : "=d"(r) : "d"(a), "d"(b)); return r;
}

// ---------------- mma / smem helpers ------------------------------------------
__device__ __forceinline__ uint32_t smem_u32(const void* p) {
    uint32_t a;
    asm("{ .reg .u64 t; cvta.to.shared.u64 t, %1; cvt.u32.u64 %0, t; }" : "=r"(a) : "l"(p));
    return a;
}
__device__ __forceinline__ void cp_async16(uint32_t dst, const void* src) {
    asm volatile("cp.async.cg.shared.global [%0], [%1], 16;"
                 :: "r"(dst), "l"(src) : "memory");
}
__device__ __forceinline__ void ldsm4(uint32_t r[4], uint32_t addr) {
    asm volatile("ldmatrix.sync.aligned.m8n8.x4.shared.b16 {%0,%1,%2,%3}, [%4];"
                 : "=r"(r[0]), "=r"(r[1]), "=r"(r[2]), "=r"(r[3]) : "r"(addr));
}
__device__ __forceinline__ void mma16816(float c[4], const uint32_t a[4],
                                         uint32_t b0, uint32_t b1) {
    asm volatile(
        "mma.sync.aligned.m16n8k16.row.col.f32.f16.f16.f32 "
        "{%0,%1,%2,%3}, {%4,%5,%6,%7}, {%8,%9}, {%0,%1,%2,%3};"
        : "+f"(c[0]), "+f"(c[1]), "+f"(c[2]), "+f"(c[3])
        : "r"(a[0]), "r"(a[1]), "r"(a[2]), "r"(a[3]), "r"(b0), "r"(b1));
}
__device__ __forceinline__ int ld_acq(const int* p) {
    int v; asm volatile("ld.acquire.gpu.global.b32 %0, [%1];" : "=r"(v) : "l"(p)); return v;
}
__device__ __forceinline__ void red_release(int* p) {
    asm volatile("red.release.gpu.global.add.s32 [%0], %1;" :: "l"(p), "r"(1) : "memory");
}
#define SW128(x) ((x) ^ (((x) >> 3) & 0x70))

__device__ __forceinline__ void store_split(__half* p, float v) {
    __half hi = __float2half_rn(v);
    p[0]   = hi;
    p[256] = __float2half_rn(v - __half2float(hi));
}

// ============================================================================
// prep_a: embed+proj | transpose W_hh | reset sync   (stream 0, feeds rnn)
// ============================================================================
#define NB_EMB 400
#define NB_TRA 256
#define NB_PREPA (NB_EMB + NB_TRA)
#define NB_PREPB (NPAD / 4)        // 2528 blocks: W_aff -> fp16

__global__ void __launch_bounds__(256)
prep_a(const int* __restrict__ xraw,
       const float* __restrict__ emb,
       const float* __restrict__ W_ih,
       const float* __restrict__ b_ih,
       const float* __restrict__ b_hh,
       const float* __restrict__ W_hh)
{
    const int bb = blockIdx.x;

    if (bb >= NB_EMB) {                          // ---- transpose W_hh ----
        int idx = (bb - NB_EMB) * 256 + threadIdx.x;  // 65536 elems
        int k = idx >> 8, j = idx & 255;
        g_WT[k * HH + j] = W_hh[j * HH + k];
        return;
    }

    // ---- embedding + input projection (16 rows per block) ----
    if (bb == 0 && threadIdx.x < SS) g_prog[threadIdx.x] = 0;   // reset progress
    if (bb == 0 && threadIdx.x == 255) g_ticket = 0;            // reset tickets

    __shared__ __align__(16) float se[16][XX];

    const bool is64 = ((xraw[1] | xraw[3] | xraw[5] | xraw[7] | xraw[9]) == 0) &&
                      ((xraw[0] | xraw[2] | xraw[4] | xraw[6] | xraw[8]) != 0);

    const int m0 = bb * 16;
    for (int i = threadIdx.x; i < 16 * (XX / 4); i += 256) {
        int r = i >> 5, c = i & 31;
        int m = m0 + r;
        int tok = is64 ? xraw[2 * m] : xraw[m];
        ((float4*)se[r])[c] = ((const float4*)(emb + (long long)tok * XX))[c];
    }
    __syncthreads();

    const int j = threadIdx.x;
    const float bias = b_ih[j] + b_hh[j];
    float acc[16];
#pragma unroll
    for (int r = 0; r < 16; r++) acc[r] = bias;

    const float* wr = W_ih + j * XX;
#pragma unroll 4
    for (int k = 0; k < XX; k += 4) {
        float4 w = *(const float4*)(wr + k);
#pragma unroll
        for (int r = 0; r < 16; r++) {
            float4 e = *(const float4*)&se[r][k];
            acc[r] = fmaf(w.x, e.x, fmaf(w.y, e.y, fmaf(w.z, e.z, fmaf(w.w, e.w, acc[r]))));
        }
    }
#pragma unroll
    for (int r = 0; r < 16; r++)
        g_xin[(m0 + r) * HH + j] = acc[r];
}

// ============================================================================
// prep_b: W_aff -> fp16  (stream s2, concurrent with prep_a; precedes consumers)
// ============================================================================
__global__ void __launch_bounds__(256)
prep_b(const float* __restrict__ Wa)
{
    int idx = blockIdx.x * 256 + threadIdx.x;   // NPAD * 64
    int n  = idx >> 6;
    int k4 = (idx & 63) << 2;
    float4 w = make_float4(0.f, 0.f, 0.f, 0.f);
    if (n < VV) w = *(const float4*)(Wa + (size_t)n * 256 + k4);
    __half* p = g_B2 + (size_t)n * 256 + k4;
    p[0] = __float2half_rn(w.x);
    p[1] = __float2half_rn(w.y);
    p[2] = __float2half_rn(w.z);
    p[3] = __float2half_rn(w.w);
}

// ============================================================================
// Persistent GEMM consumer loop (identical to R14).
//   C[m][n] = A_hi.B + A_lo.B + bias   (fp16 x fp16 -> fp32, K_eff = 512)
//   Chunk order ch = 2*s + seg: B(s) shared by the chunk pair (B ring 2-deep).
// ============================================================================
#define RNN_W_F2   (128 * 64)            // float2: quarter of W
#define RNN_HB_F2  (2 * 4 * 256)         // [buf][rq][col]
#define A_TILE 16384
#define NSTAGE_A 3
#define NSTAGE_B 2
#define SMEM_TILES ((NSTAGE_A + NSTAGE_B) * A_TILE)   // 81920 == rnn's 80 KB
#define NB_RNN 64
#define NB_GEMM 232
#define NCHUNK 8

__device__ void consume_tiles(const float* __restrict__ ba, float* __restrict__ C,
                              char* smem, int tid)
{
    const uint32_t sb  = smem_u32(smem);
    const uint32_t sbB = sb + NSTAGE_A * A_TILE;
    const int wid  = tid >> 5;
    const int lane = tid & 31;

    uint32_t t_sw[4];
    int l_row[4], l_c[4];
#pragma unroll
    for (int i = 0; i < 4; i++) {
        int idx = i * 256 + tid;
        l_row[i] = idx >> 3; l_c[i] = idx & 7;
        t_sw[i] = SW128(l_row[i] * 128 + l_c[i] * 16);
    }

    const int wm0 = (wid >> 1) * 32;
    const int wn0 = (wid & 1) * 64;
    const int a_row  = wm0 + (lane & 7) + ((lane & 8) ? 8 : 0);
    const int a_koff = (lane & 16) ? 16 : 0;
    const int b_row  = wn0 + (lane & 7) + ((lane & 16) ? 8 : 0);
    const int b_koff = (lane & 8) ? 16 : 0;
    const int lm = lane >> 2;
    const int lq = (lane & 3) * 2;

    __shared__ int s_ticket;

    for (;;) {
        if (tid == 0) s_ticket = atomicAdd(&g_ticket, 1);
        __syncthreads();
        const int ticket = s_ticket;
        __syncthreads();
        if (ticket >= N_TICKETS) return;

        const int tT = ticket / NT_N;
        const int bn = (ticket % NT_N) * 128;
        const int bm = tT * 128;

        if (tid == 0) {
            while (ld_acq(&g_prog[tT]) < NB_RNN) __nanosleep(128);
        }
        __syncthreads();

        const __half* a_src[4];
        const __half* b_src[4];
#pragma unroll
        for (int i = 0; i < 4; i++) {
            a_src[i] = g_A2 + (size_t)(bm + l_row[i]) * 512 + l_c[i] * 8;
            b_src[i] = g_B2 + (size_t)(bn + l_row[i]) * 256 + l_c[i] * 8;
        }

        float acc[2][8][4];
#pragma unroll
        for (int mt = 0; mt < 2; mt++)
#pragma unroll
            for (int nt = 0; nt < 8; nt++)
#pragma unroll
                for (int q = 0; q < 4; q++) acc[mt][nt][q] = 0.f;

        // ch = 2*s + seg: s = ch>>1 (k-quarter), seg = ch&1 (A hi/lo).
        // A -> ring ch%3; B(s) loaded on even ch -> ring (ch>>1)&1.
        auto prefetch = [&](int ch) {
            const int s = ch >> 1, seg = ch & 1;
            const int aoff = seg * 256 + s * 64;
            const uint32_t abase = sb + (ch % NSTAGE_A) * A_TILE;
#pragma unroll
            for (int i = 0; i < 4; i++) cp_async16(abase + t_sw[i], a_src[i] + aoff);
            if (!seg) {
                const uint32_t bbase = sbB + (s & 1) * A_TILE;
#pragma unroll
                for (int i = 0; i < 4; i++) cp_async16(bbase + t_sw[i], b_src[i] + s * 64);
            }
            asm volatile("cp.async.commit_group;" ::: "memory");
        };

        prefetch(0);
        prefetch(1);

#pragma unroll 1
        for (int ch = 0; ch < NCHUNK; ++ch) {
            if (ch < NCHUNK - 1) asm volatile("cp.async.wait_group 1;" ::: "memory");
            else                 asm volatile("cp.async.wait_group 0;" ::: "memory");
            __syncthreads();
            if (ch + 2 < NCHUNK) prefetch(ch + 2);

            const uint32_t Ab = sb  + (ch % NSTAGE_A) * A_TILE;
            const uint32_t Bb = sbB + ((ch >> 1) & 1) * A_TILE;

#pragma unroll
            for (int ks = 0; ks < 4; ++ks) {
                const int kb = ks * 32;
                uint32_t a[2][4], b[4][4];
#pragma unroll
                for (int mt = 0; mt < 2; mt++)
                    ldsm4(a[mt], Ab + SW128((a_row + mt * 16) * 128 + kb + a_koff));
#pragma unroll
                for (int p = 0; p < 4; p++)
                    ldsm4(b[p], Bb + SW128((b_row + p * 16) * 128 + kb + b_koff));
#pragma unroll
                for (int mt = 0; mt < 2; mt++)
#pragma unroll
                    for (int p = 0; p < 4; p++) {
                        mma16816(acc[mt][2 * p + 0], a[mt], b[p][0], b[p][1]);
                        mma16816(acc[mt][2 * p + 1], a[mt], b[p][2], b[p][3]);
                    }
            }
        }

        // epilogue: C row for tile-local row b is m_orig = b*SS + tT
#pragma unroll
        for (int nt = 0; nt < 8; nt++) {
            const int gcol = bn + wn0 + nt * 8 + lq;
            if (gcol >= VV) continue;
            const float2 bv = *(const float2*)(ba + gcol);
#pragma unroll
            for (int mt = 0; mt < 2; mt++) {
                const int brow = wm0 + mt * 16 + lm;             // batch index
                float* c0 = C + ((size_t)brow * SS + tT) * VV + gcol;
                float2 o0 = make_float2(acc[mt][nt][0] + bv.x, acc[mt][nt][1] + bv.y);
                float2 o1 = make_float2(acc[mt][nt][2] + bv.x, acc[mt][nt][3] + bv.y);
                *(float2*)c0                         = o0;
                *(float2*)(c0 + (size_t)8 * SS * VV) = o1;       // brow+8
            }
        }
        __syncthreads();
    }
}

// ============================================================================
// RNN kernel (cluster-4, 64 CTAs), R12/R14 lane mapping (rq=tid>>6, jl=tid&63).
// After the scan, CTAs become gemm consumers.
// ============================================================================
__global__ void __launch_bounds__(256, 2) __cluster_dims__(4, 1, 1)
rnn_then_consume(const float* __restrict__ ba, float* __restrict__ C)
{
    extern __shared__ __align__(1024) char smem[];
    const int bid = blockIdx.x;
    const int tid = threadIdx.x;

    {
        float2* wsp = (float2*)smem;            // [k2*64 + jl], k2=0..127
        float2* hb  = (float2*)smem + RNN_W_F2; // [(buf*4 + rq)*256 + col]
        const uint32_t hb_addr = smem_u32(hb);

        const int rq   = tid >> 6;              // rowpair 0..3
        const int jl   = tid & 63;
        const uint32_t rank = bid & 3;
        const int jg   = rank * 64 + jl;        // global output column
        const int b0   = (bid >> 2) * 8;        // 8 batch rows per cluster

        for (int i = tid; i < RNN_W_F2; i += 256) {
            int k2 = i >> 6, j = i & 63;
            int jgl = rank * 64 + j;
            wsp[i] = make_float2(g_WT[(2 * k2) * HH + jgl],
                                 g_WT[(2 * k2 + 1) * HH + jgl]);
        }
        for (int i = tid; i < 4 * 256; i += 256) hb[i] = make_float2(0.f, 0.f);

        asm volatile("barrier.cluster.arrive.aligned;" ::: "memory");
        asm volatile("barrier.cluster.wait.aligned;" ::: "memory");

        const int r0 = b0 + 2 * rq;
        const float* x0p = g_xin + (size_t)r0 * SS * HH + jg;
        const float* x1p = g_xin + (size_t)(r0 + 1) * SS * HH + jg;
        __half* a0p = g_A2 + (size_t)r0 * 512 + jg;        // + t*BB*512
        __half* a1p = g_A2 + (size_t)(r0 + 1) * 512 + jg;

        const float2* wp = wsp + jl;
        const uint32_t p1 = rank ^ 1, p2 = rank ^ 2, p3 = rank ^ 3;

        float xa = x0p[0], xb = x1p[0];
        int cur = 0;
        for (int t = 0; t < SS; ++t) {
            double acc_e = pk2(xa, xb);
            double acc_o = 0.0;
            if (t + 1 < SS) {
                xa = x0p[(size_t)(t + 1) * HH];
                xb = x1p[(size_t)(t + 1) * HH];
            }

            const double2* hc = (const double2*)(hb + (cur * 4 + rq) * 256);
#pragma unroll 8
            for (int k2 = 0; k2 < 128; ++k2) {
                float2 wv  = wp[k2 * 64];
                double2 h2 = hc[k2];
                ffma2(acc_e, dup2(wv.x), h2.x);
                ffma2(acc_o, dup2(wv.y), h2.y);
            }

            float2 f = unpk(fadd2(acc_e, acc_o));
            float h0 = tanhf(f.x), h1 = tanhf(f.y);

            const int nxt = cur ^ 1;
            const long long hp = __double_as_longlong(pk2(h0, h1));
            uint32_t loc = hb_addr + (uint32_t)(((nxt * 4 + rq) * 256 + jg) * 8);
            asm volatile("st.shared.b64 [%0], %1;" :: "r"(loc), "l"(hp) : "memory");
            asm volatile(
                "{\n\t.reg .b32 ra;\n\t"
                "mapa.shared::cluster.u32 ra, %0, %1;\n\t"
                "st.shared::cluster.b64 [ra], %2;\n\t"
                "mapa.shared::cluster.u32 ra, %0, %3;\n\t"
                "st.shared::cluster.b64 [ra], %2;\n\t"
                "mapa.shared::cluster.u32 ra, %0, %4;\n\t"
                "st.shared::cluster.b64 [ra], %2;\n\t}"
                :: "r"(loc), "r"(p1), "l"(hp), "r"(p2), "r"(p3) : "memory");

            store_split(a0p + (size_t)t * (BB * 512), h0);
            store_split(a1p + (size_t)t * (BB * 512), h1);

            asm volatile("barrier.cluster.arrive.aligned;" ::: "memory");
            asm volatile("barrier.cluster.wait.aligned;" ::: "memory");
            if (tid == 0) red_release(&g_prog[t]);
            cur = nxt;
        }
    }
    __syncthreads();
    // Scan done: convert this CTA into a gemm consumer (reuses smem).
    consume_tiles(ba, C, smem, tid);
}

// ============================================================================
// Pure consumer kernel (no cluster -> full scheduling flexibility)
// ============================================================================
__global__ void __launch_bounds__(256, 2)
gemm_consume(const float* __restrict__ ba, float* __restrict__ C)
{
    extern __shared__ __align__(1024) char smem[];
    consume_tiles(ba, C, smem, threadIdx.x);
}

// ============================================================================
extern "C" void kernel_launch(void* const* d_in, const int* in_sizes, int n_in,
                              void* d_out, int out_size)
{
    const int*   x     = (const int*)  d_in[0];
    const float* emb   = (const float*)d_in[1];
    const float* W_ih  = (const float*)d_in[2];
    const float* W_hh  = (const float*)d_in[3];
    const float* b_ih  = (const float*)d_in[4];
    const float* b_hh  = (const float*)d_in[5];
    const float* W_aff = (const float*)d_in[6];
    const float* b_aff = (const float*)d_in[7];
    float* out = (float*)d_out;

    static cudaStream_t s2 = nullptr;
    static cudaEvent_t evF = nullptr, evA = nullptr, evB = nullptr;
    if (s2 == nullptr) {
        cudaStreamCreateWithFlags(&s2, cudaStreamNonBlocking);
        cudaEventCreateWithFlags(&evF, cudaEventDisableTiming);
        cudaEventCreateWithFlags(&evA, cudaEventDisableTiming);
        cudaEventCreateWithFlags(&evB, cudaEventDisableTiming);
        cudaFuncSetAttribute(rnn_then_consume,
                             cudaFuncAttributeMaxDynamicSharedMemorySize, SMEM_TILES);
        cudaFuncSetAttribute(gemm_consume,
                             cudaFuncAttributeMaxDynamicSharedMemorySize, SMEM_TILES);
    }

    // fork s2 off the capture stream
    cudaEventRecord(evF, 0);
    cudaStreamWaitEvent(s2, evF, 0);

    prep_a<<<NB_PREPA, 256>>>(x, emb, W_ih, b_ih, b_hh, W_hh);   // stream 0
    prep_b<<<NB_PREPB, 256, 0, s2>>>(W_aff);                     // stream s2 (concurrent)

    cudaEventRecord(evA, 0);                 // prep_a (incl. sync resets) done
    cudaStreamWaitEvent(s2, evA, 0);         // consumers need resets before spinning

    rnn_then_consume<<<NB_RNN, 256, SMEM_TILES>>>(b_aff, out);          // stream 0
    gemm_consume<<<NB_GEMM, 256, SMEM_TILES, s2>>>(b_aff, out);         // stream s2

    // join
    cudaEventRecord(evB, s2);
    cudaStreamWaitEvent(0, evB, 0);
}

// round 16
// speedup vs baseline: 1.1505x; 1.0520x over previous
#include <cuda_runtime.h>
#include <cuda_fp16.h>
#include <cstdint>

#define BB 128
#define SS 50
#define XX 128
#define HH 256
#define VV 10000
#define MM (BB*SS)     // 6400
#define NT_N 79
#define NPAD (NT_N * 128)   // 10112
#define N_TICKETS (SS * NT_N)

// ---------------- device scratch (no allocs allowed in kernel_launch) ------
__device__ float g_xin[MM * HH];                         // input projection [b][t][j]
__device__ float g_WT[HH * HH];                          // W_hh transposed: [k][j]
// t-MAJOR: row m = t*128 + b ; fp16 h (single precision level, no split)
__device__ __align__(16) __half g_A2[MM * 256];
__device__ __align__(16) __half g_B2[(size_t)NPAD * 256];   // W_aff in plain fp16
__device__ int g_prog[SS];                               // per-step producer arrivals
__device__ int g_ticket;                                 // persistent consumer tickets

// ---------------- packed fp32x2 helpers --------------------------------------
__device__ __forceinline__ double dup2(float x) {
    double r; asm("mov.b64 %0, {%1, %1};" : "=d"(r) : "f"(x)); return r;
}
__device__ __forceinline__ double pk2(float lo, float hi) {
    double r; asm("mov.b64 %0, {%1, %2};" : "=d"(r) : "f"(lo), "f"(hi)); return r;
}
__device__ __forceinline__ float2 unpk(double d) {
    float2 f; asm("mov.b64 {%0, %1}, %2;" : "=f"(f.x), "=f"(f.y) : "d"(d)); return f;
}
__device__ __forceinline__ void ffma2(double& acc, double a, double b) {
    asm("fma.rn.f32x2 %0, %1, %2, %0;" : "+d"(acc) : "d"(a), "d"(b));
}
__device__ __forceinline__ double fadd2(double a, double b) {
    double r; asm("add.rn.f32x2 %0, %1, %2;" : "=d"(r) : "d"(a), "d"(b)); return r;
}

// ---------------- mma / smem helpers ------------------------------------------
__device__ __forceinline__ uint32_t smem_u32(const void* p) {
    uint32_t a;
    asm("{ .reg .u64 t; cvta.to.shared.u64 t, %1; cvt.u32.u64 %0, t; }" : "=r"(a) : "l"(p));
    return a;
}
__device__ __forceinline__ void cp_async16(uint32_t dst, const void* src) {
    asm volatile("cp.async.cg.shared.global [%0], [%1], 16;"
                 :: "r"(dst), "l"(src) : "memory");
}
__device__ __forceinline__ void ldsm4(uint32_t r[4], uint32_t addr) {
    asm volatile("ldmatrix.sync.aligned.m8n8.x4.shared.b16 {%0,%1,%2,%3}, [%4];"
                 : "=r"(r[0]), "=r"(r[1]), "=r"(r[2]), "=r"(r[3]) : "r"(addr));
}
__device__ __forceinline__ void mma16816(float c[4], const uint32_t a[4],
                                         uint32_t b0, uint32_t b1) {
    asm volatile(
        "mma.sync.aligned.m16n8k16.row.col.f32.f16.f16.f32 "
        "{%0,%1,%2,%3}, {%4,%5,%6,%7}, {%8,%9}, {%0,%1,%2,%3};"
        : "+f"(c[0]), "+f"(c[1]), "+f"(c[2]), "+f"(c[3])
        : "r"(a[0]), "r"(a[1]), "r"(a[2]), "r"(a[3]), "r"(b0), "r"(b1));
}
__device__ __forceinline__ int ld_acq(const int* p) {
    int v; asm volatile("ld.acquire.gpu.global.b32 %0, [%1];" : "=r"(v) : "l"(p)); return v;
}
__device__ __forceinline__ void red_release(int* p) {
    asm volatile("red.release.gpu.global.add.s32 [%0], %1;" :: "l"(p), "r"(1) : "memory");
}
#define SW128(x) ((x) ^ (((x) >> 3) & 0x70))

// ============================================================================
// prep_a: embed+proj | transpose W_hh | reset sync   (stream 0, feeds rnn)
// ============================================================================
#define NB_EMB 400
#define NB_TRA 256
#define NB_PREPA (NB_EMB + NB_TRA)
#define NB_PREPB (NPAD / 4)        // 2528 blocks: W_aff -> fp16

__global__ void __launch_bounds__(256)
prep_a(const int* __restrict__ xraw,
       const float* __restrict__ emb,
       const float* __restrict__ W_ih,
       const float* __restrict__ b_ih,
       const float* __restrict__ b_hh,
       const float* __restrict__ W_hh)
{
    const int bb = blockIdx.x;

    if (bb >= NB_EMB) {                          // ---- transpose W_hh ----
        int idx = (bb - NB_EMB) * 256 + threadIdx.x;  // 65536 elems
        int k = idx >> 8, j = idx & 255;
        g_WT[k * HH + j] = W_hh[j * HH + k];
        return;
    }

    // ---- embedding + input projection (16 rows per block) ----
    if (bb == 0 && threadIdx.x < SS) g_prog[threadIdx.x] = 0;   // reset progress
    if (bb == 0 && threadIdx.x == 255) g_ticket = 0;            // reset tickets

    __shared__ __align__(16) float se[16][XX];

    const bool is64 = ((xraw[1] | xraw[3] | xraw[5] | xraw[7] | xraw[9]) == 0) &&
                      ((xraw[0] | xraw[2] | xraw[4] | xraw[6] | xraw[8]) != 0);

    const int m0 = bb * 16;
    for (int i = threadIdx.x; i < 16 * (XX / 4); i += 256) {
        int r = i >> 5, c = i & 31;
        int m = m0 + r;
        int tok = is64 ? xraw[2 * m] : xraw[m];
        ((float4*)se[r])[c] = ((const float4*)(emb + (long long)tok * XX))[c];
    }
    __syncthreads();

    const int j = threadIdx.x;
    const float bias = b_ih[j] + b_hh[j];
    float acc[16];
#pragma unroll
    for (int r = 0; r < 16; r++) acc[r] = bias;

    const float* wr = W_ih + j * XX;
#pragma unroll 4
    for (int k = 0; k < XX; k += 4) {
        float4 w = *(const float4*)(wr + k);
#pragma unroll
        for (int r = 0; r < 16; r++) {
            float4 e = *(const float4*)&se[r][k];
            acc[r] = fmaf(w.x, e.x, fmaf(w.y, e.y, fmaf(w.z, e.z, fmaf(w.w, e.w, acc[r]))));
        }
    }
#pragma unroll
    for (int r = 0; r < 16; r++)
        g_xin[(m0 + r) * HH + j] = acc[r];
}

// ============================================================================
// prep_b: W_aff -> fp16  (stream s2, concurrent with prep_a; precedes consumers)
// ============================================================================
__global__ void __launch_bounds__(256)
prep_b(const float* __restrict__ Wa)
{
    int idx = blockIdx.x * 256 + threadIdx.x;   // NPAD * 64
    int n  = idx >> 6;
    int k4 = (idx & 63) << 2;
    float4 w = make_float4(0.f, 0.f, 0.f, 0.f);
    if (n < VV) w = *(const float4*)(Wa + (size_t)n * 256 + k4);
    __half* p = g_B2 + (size_t)n * 256 + k4;
    p[0] = __float2half_rn(w.x);
    p[1] = __float2half_rn(w.y);
    p[2] = __float2half_rn(w.z);
    p[3] = __float2half_rn(w.w);
}

// ============================================================================
// Persistent GEMM consumer loop — single-pass fp16, K = 256, 4 chunks of 64.
//   C[m][n] = fp16(h).fp16(W_aff) + bias   (fp32 accum in mma)
//   Stage = 32 KB (A 16 KB | B 16 KB), ring of 3 (96 KB total, 2 CTAs/SM
//   proven at this footprint in R12).
// ============================================================================
#define RNN_W_F2   (128 * 64)            // float2: quarter of W
#define RNN_HB_F2  (2 * 4 * 256)         // [buf][rq][col]
#define HALF_TILE 16384
#define STAGE_BYTES (2 * HALF_TILE)      // A + B
#define NSTAGE 3
#define SMEM_TILES (NSTAGE * STAGE_BYTES)   // 98304 (rnn scan uses 80 KB subset)
#define NB_RNN 64
#define NB_GEMM 232
#define NCHUNK 4

__device__ void consume_tiles(const float* __restrict__ ba, float* __restrict__ C,
                              char* smem, int tid)
{
    const uint32_t sb = smem_u32(smem);
    const int wid  = tid >> 5;
    const int lane = tid & 31;

    uint32_t t_sw[4];
    int l_row[4], l_c[4];
#pragma unroll
    for (int i = 0; i < 4; i++) {
        int idx = i * 256 + tid;
        l_row[i] = idx >> 3; l_c[i] = idx & 7;
        t_sw[i] = SW128(l_row[i] * 128 + l_c[i] * 16);
    }

    const int wm0 = (wid >> 1) * 32;
    const int wn0 = (wid & 1) * 64;
    const int a_row  = wm0 + (lane & 7) + ((lane & 8) ? 8 : 0);
    const int a_koff = (lane & 16) ? 16 : 0;
    const int b_row  = wn0 + (lane & 7) + ((lane & 16) ? 8 : 0);
    const int b_koff = (lane & 8) ? 16 : 0;
    const int lm = lane >> 2;
    const int lq = (lane & 3) * 2;

    __shared__ int s_ticket;

    for (;;) {
        if (tid == 0) s_ticket = atomicAdd(&g_ticket, 1);
        __syncthreads();
        const int ticket = s_ticket;
        __syncthreads();
        if (ticket >= N_TICKETS) return;

        const int tT = ticket / NT_N;
        const int bn = (ticket % NT_N) * 128;
        const int bm = tT * 128;

        if (tid == 0) {
            while (ld_acq(&g_prog[tT]) < NB_RNN) __nanosleep(128);
        }
        __syncthreads();

        const __half* a_src[4];
        const __half* b_src[4];
#pragma unroll
        for (int i = 0; i < 4; i++) {
            a_src[i] = g_A2 + (size_t)(bm + l_row[i]) * 256 + l_c[i] * 8;
            b_src[i] = g_B2 + (size_t)(bn + l_row[i]) * 256 + l_c[i] * 8;
        }

        float acc[2][8][4];
#pragma unroll
        for (int mt = 0; mt < 2; mt++)
#pragma unroll
            for (int nt = 0; nt < 8; nt++)
#pragma unroll
                for (int q = 0; q < 4; q++) acc[mt][nt][q] = 0.f;

        // chunk ch = k-quarter; stage ring (ch % 3): prefetch(ch+2) never
        // touches the stages being read by compute(ch) or compute(ch+1).
        auto prefetch = [&](int ch) {
            const int off = ch * 64;
            const uint32_t base = sb + (ch % NSTAGE) * STAGE_BYTES;
#pragma unroll
            for (int i = 0; i < 4; i++) cp_async16(base + t_sw[i], a_src[i] + off);
#pragma unroll
            for (int i = 0; i < 4; i++) cp_async16(base + HALF_TILE + t_sw[i], b_src[i] + off);
            asm volatile("cp.async.commit_group;" ::: "memory");
        };

        prefetch(0);
        prefetch(1);

#pragma unroll 1
        for (int ch = 0; ch < NCHUNK; ++ch) {
            if (ch < NCHUNK - 1) asm volatile("cp.async.wait_group 1;" ::: "memory");
            else                 asm volatile("cp.async.wait_group 0;" ::: "memory");
            __syncthreads();
            if (ch + 2 < NCHUNK) prefetch(ch + 2);

            const uint32_t Ab = sb + (ch % NSTAGE) * STAGE_BYTES;
            const uint32_t Bb = Ab + HALF_TILE;

#pragma unroll
            for (int ks = 0; ks < 4; ++ks) {
                const int kb = ks * 32;
                uint32_t a[2][4], b[4][4];
#pragma unroll
                for (int mt = 0; mt < 2; mt++)
                    ldsm4(a[mt], Ab + SW128((a_row + mt * 16) * 128 + kb + a_koff));
#pragma unroll
                for (int p = 0; p < 4; p++)
                    ldsm4(b[p], Bb + SW128((b_row + p * 16) * 128 + kb + b_koff));
#pragma unroll
                for (int mt = 0; mt < 2; mt++)
#pragma unroll
                    for (int p = 0; p < 4; p++) {
                        mma16816(acc[mt][2 * p + 0], a[mt], b[p][0], b[p][1]);
                        mma16816(acc[mt][2 * p + 1], a[mt], b[p][2], b[p][3]);
                    }
            }
        }

        // epilogue: C row for tile-local row b is m_orig = b*SS + tT
#pragma unroll
        for (int nt = 0; nt < 8; nt++) {
            const int gcol = bn + wn0 + nt * 8 + lq;
            if (gcol >= VV) continue;
            const float2 bv = *(const float2*)(ba + gcol);
#pragma unroll
            for (int mt = 0; mt < 2; mt++) {
                const int brow = wm0 + mt * 16 + lm;             // batch index
                float* c0 = C + ((size_t)brow * SS + tT) * VV + gcol;
                float2 o0 = make_float2(acc[mt][nt][0] + bv.x, acc[mt][nt][1] + bv.y);
                float2 o1 = make_float2(acc[mt][nt][2] + bv.x, acc[mt][nt][3] + bv.y);
                *(float2*)c0                         = o0;
                *(float2*)(c0 + (size_t)8 * SS * VV) = o1;       // brow+8
            }
        }
        __syncthreads();
    }
}

// ============================================================================
// RNN kernel (cluster-4, 64 CTAs), R12/R14 lane mapping (rq=tid>>6, jl=tid&63).
// h stored as single fp16 (no split). After the scan, CTAs become consumers.
// ============================================================================
__global__ void __launch_bounds__(256, 2) __cluster_dims__(4, 1, 1)
rnn_then_consume(const float* __restrict__ ba, float* __restrict__ C)
{
    extern __shared__ __align__(1024) char smem[];
    const int bid = blockIdx.x;
    const int tid = threadIdx.x;

    {
        float2* wsp = (float2*)smem;            // [k2*64 + jl], k2=0..127
        float2* hb  = (float2*)smem + RNN_W_F2; // [(buf*4 + rq)*256 + col]
        const uint32_t hb_addr = smem_u32(hb);

        const int rq   = tid >> 6;              // rowpair 0..3
        const int jl   = tid & 63;
        const uint32_t rank = bid & 3;
        const int jg   = rank * 64 + jl;        // global output column
        const int b0   = (bid >> 2) * 8;        // 8 batch rows per cluster

        for (int i = tid; i < RNN_W_F2; i += 256) {
            int k2 = i >> 6, j = i & 63;
            int jgl = rank * 64 + j;
            wsp[i] = make_float2(g_WT[(2 * k2) * HH + jgl],
                                 g_WT[(2 * k2 + 1) * HH + jgl]);
        }
        for (int i = tid; i < 4 * 256; i += 256) hb[i] = make_float2(0.f, 0.f);

        asm volatile("barrier.cluster.arrive.aligned;" ::: "memory");
        asm volatile("barrier.cluster.wait.aligned;" ::: "memory");

        const int r0 = b0 + 2 * rq;
        const float* x0p = g_xin + (size_t)r0 * SS * HH + jg;
        const float* x1p = g_xin + (size_t)(r0 + 1) * SS * HH + jg;
        __half* a0p = g_A2 + (size_t)r0 * 256 + jg;        // + t*BB*256
        __half* a1p = g_A2 + (size_t)(r0 + 1) * 256 + jg;

        const float2* wp = wsp + jl;
        const uint32_t p1 = rank ^ 1, p2 = rank ^ 2, p3 = rank ^ 3;

        float xa = x0p[0], xb = x1p[0];
        int cur = 0;
        for (int t = 0; t < SS; ++t) {
            double acc_e = pk2(xa, xb);
            double acc_o = 0.0;
            if (t + 1 < SS) {
                xa = x0p[(size_t)(t + 1) * HH];
                xb = x1p[(size_t)(t + 1) * HH];
            }

            const double2* hc = (const double2*)(hb + (cur * 4 + rq) * 256);
#pragma unroll 8
            for (int k2 = 0; k2 < 128; ++k2) {
                float2 wv  = wp[k2 * 64];
                double2 h2 = hc[k2];
                ffma2(acc_e, dup2(wv.x), h2.x);
                ffma2(acc_o, dup2(wv.y), h2.y);
            }

            float2 f = unpk(fadd2(acc_e, acc_o));
            float h0 = tanhf(f.x), h1 = tanhf(f.y);

            const int nxt = cur ^ 1;
            const long long hp = __double_as_longlong(pk2(h0, h1));
            uint32_t loc = hb_addr + (uint32_t)(((nxt * 4 + rq) * 256 + jg) * 8);
            asm volatile("st.shared.b64 [%0], %1;" :: "r"(loc), "l"(hp) : "memory");
            asm volatile(
                "{\n\t.reg .b32 ra;\n\t"
                "mapa.shared::cluster.u32 ra, %0, %1;\n\t"
                "st.shared::cluster.b64 [ra], %2;\n\t"
                "mapa.shared::cluster.u32 ra, %0, %3;\n\t"
                "st.shared::cluster.b64 [ra], %2;\n\t"
                "mapa.shared::cluster.u32 ra, %0, %4;\n\t"
                "st.shared::cluster.b64 [ra], %2;\n\t}"
                :: "r"(loc), "r"(p1), "l"(hp), "r"(p2), "r"(p3) : "memory");

            a0p[(size_t)t * (BB * 256)] = __float2half_rn(h0);
            a1p[(size_t)t * (BB * 256)] = __float2half_rn(h1);

            asm volatile("barrier.cluster.arrive.aligned;" ::: "memory");
            asm volatile("barrier.cluster.wait.aligned;" ::: "memory");
            if (tid == 0) red_release(&g_prog[t]);
            cur = nxt;
        }
    }
    __syncthreads();
    // Scan done: convert this CTA into a gemm consumer (reuses smem).
    consume_tiles(ba, C, smem, tid);
}

// ============================================================================
// Pure consumer kernel (no cluster -> full scheduling flexibility)
// ============================================================================
__global__ void __launch_bounds__(256, 2)
gemm_consume(const float* __restrict__ ba, float* __restrict__ C)
{
    extern __shared__ __align__(1024) char smem[];
    consume_tiles(ba, C, smem, threadIdx.x);
}

// ============================================================================
extern "C" void kernel_launch(void* const* d_in, const int* in_sizes, int n_in,
                              void* d_out, int out_size)
{
    const int*   x     = (const int*)  d_in[0];
    const float* emb   = (const float*)d_in[1];
    const float* W_ih  = (const float*)d_in[2];
    const float* W_hh  = (const float*)d_in[3];
    const float* b_ih  = (const float*)d_in[4];
    const float* b_hh  = (const float*)d_in[5];
    const float* W_aff = (const float*)d_in[6];
    const float* b_aff = (const float*)d_in[7];
    float* out = (float*)d_out;

    static cudaStream_t s2 = nullptr;
    static cudaEvent_t evF = nullptr, evA = nullptr, evB = nullptr;
    if (s2 == nullptr) {
        cudaStreamCreateWithFlags(&s2, cudaStreamNonBlocking);
        cudaEventCreateWithFlags(&evF, cudaEventDisableTiming);
        cudaEventCreateWithFlags(&evA, cudaEventDisableTiming);
        cudaEventCreateWithFlags(&evB, cudaEventDisableTiming);
        cudaFuncSetAttribute(rnn_then_consume,
                             cudaFuncAttributeMaxDynamicSharedMemorySize, SMEM_TILES);
        cudaFuncSetAttribute(gemm_consume,
                             cudaFuncAttributeMaxDynamicSharedMemorySize, SMEM_TILES);
    }

    // fork s2 off the capture stream
    cudaEventRecord(evF, 0);
    cudaStreamWaitEvent(s2, evF, 0);

    prep_a<<<NB_PREPA, 256>>>(x, emb, W_ih, b_ih, b_hh, W_hh);   // stream 0
    prep_b<<<NB_PREPB, 256, 0, s2>>>(W_aff);                     // stream s2 (concurrent)

    cudaEventRecord(evA, 0);                 // prep_a (incl. sync resets) done
    cudaStreamWaitEvent(s2, evA, 0);         // consumers need resets before spinning

    rnn_then_consume<<<NB_RNN, 256, SMEM_TILES>>>(b_aff, out);          // stream 0
    gemm_consume<<<NB_GEMM, 256, SMEM_TILES, s2>>>(b_aff, out);         // stream s2

    // join
    cudaEventRecord(evB, s2);
    cudaStreamWaitEvent(0, evB, 0);
}

// round 17
// speedup vs baseline: 1.3270x; 1.1534x over previous
#include <cuda_runtime.h>
#include <cuda_fp16.h>
#include <cstdint>

#define BB 128
#define SS 50
#define XX 128
#define HH 256
#define VV 10000
#define MM (BB*SS)     // 6400
#define NT_N 79
#define NPAD (NT_N * 128)   // 10112
#define N_TICKETS (SS * NT_N)

// ---------------- device scratch (no allocs allowed in kernel_launch) ------
__device__ float g_xin[MM * HH];                         // input projection [b][t][j]
__device__ float g_WT[HH * HH];                          // W_hh transposed: [k][j]
// t-MAJOR: row m = t*128 + b ; fp16 h (single precision level, no split)
__device__ __align__(16) __half g_A2[MM * 256];
__device__ __align__(16) __half g_B2[(size_t)NPAD * 256];   // W_aff in plain fp16
__device__ int g_prog[SS];                               // per-step producer arrivals
__device__ int g_ticket;                                 // persistent consumer tickets

// ---------------- packed fp32x2 helpers --------------------------------------
__device__ __forceinline__ double dup2(float x) {
    double r; asm("mov.b64 %0, {%1, %1};" : "=d"(r) : "f"(x)); return r;
}
__device__ __forceinline__ double pk2(float lo, float hi) {
    double r; asm("mov.b64 %0, {%1, %2};" : "=d"(r) : "f"(lo), "f"(hi)); return r;
}
__device__ __forceinline__ float2 unpk(double d) {
    float2 f; asm("mov.b64 {%0, %1}, %2;" : "=f"(f.x), "=f"(f.y) : "d"(d)); return f;
}
__device__ __forceinline__ void ffma2(double& acc, double a, double b) {
    asm("fma.rn.f32x2 %0, %1, %2, %0;" : "+d"(acc) : "d"(a), "d"(b));
}
__device__ __forceinline__ double fadd2(double a, double b) {
    double r; asm("add.rn.f32x2 %0, %1, %2;" : "=d"(r) : "d"(a), "d"(b)); return r;
}

// ---------------- mma / smem helpers ------------------------------------------
__device__ __forceinline__ uint32_t smem_u32(const void* p) {
    uint32_t a;
    asm("{ .reg .u64 t; cvta.to.shared.u64 t, %1; cvt.u32.u64 %0, t; }" : "=r"(a) : "l"(p));
    return a;
}
__device__ __forceinline__ void cp_async16(uint32_t dst, const void* src) {
    asm volatile("cp.async.cg.shared.global [%0], [%1], 16;"
                 :: "r"(dst), "l"(src) : "memory");
}
__device__ __forceinline__ void ldsm4(uint32_t r[4], uint32_t addr) {
    asm volatile("ldmatrix.sync.aligned.m8n8.x4.shared.b16 {%0,%1,%2,%3}, [%4];"
                 : "=r"(r[0]), "=r"(r[1]), "=r"(r[2]), "=r"(r[3]) : "r"(addr));
}
__device__ __forceinline__ void mma16816(float c[4], const uint32_t a[4],
                                         uint32_t b0, uint32_t b1) {
    asm volatile(
        "mma.sync.aligned.m16n8k16.row.col.f32.f16.f16.f32 "
        "{%0,%1,%2,%3}, {%4,%5,%6,%7}, {%8,%9}, {%0,%1,%2,%3};"
        : "+f"(c[0]), "+f"(c[1]), "+f"(c[2]), "+f"(c[3])
        : "r"(a[0]), "r"(a[1]), "r"(a[2]), "r"(a[3]), "r"(b0), "r"(b1));
}
__device__ __forceinline__ int ld_acq(const int* p) {
    int v; asm volatile("ld.acquire.gpu.global.b32 %0, [%1];" : "=r"(v) : "l"(p)); return v;
}
__device__ __forceinline__ void red_release(int* p) {
    asm volatile("red.release.gpu.global.add.s32 [%0], %1;" :: "l"(p), "r"(1) : "memory");
}
#define SW128(x) ((x) ^ (((x) >> 3) & 0x70))

// ============================================================================
// prep_a: embed+proj | transpose W_hh | reset sync   (stream 0, feeds rnn)
// ============================================================================
#define NB_EMB 400
#define NB_TRA 256
#define NB_PREPA (NB_EMB + NB_TRA)
#define NB_PREPB (NPAD / 4)        // 2528 blocks: W_aff -> fp16

__global__ void __launch_bounds__(256)
prep_a(const int* __restrict__ xraw,
       const float* __restrict__ emb,
       const float* __restrict__ W_ih,
       const float* __restrict__ b_ih,
       const float* __restrict__ b_hh,
       const float* __restrict__ W_hh)
{
    const int bb = blockIdx.x;

    if (bb >= NB_EMB) {                          // ---- transpose W_hh ----
        int idx = (bb - NB_EMB) * 256 + threadIdx.x;  // 65536 elems
        int k = idx >> 8, j = idx & 255;
        g_WT[k * HH + j] = W_hh[j * HH + k];
        return;
    }

    // ---- embedding + input projection (16 rows per block) ----
    if (bb == 0 && threadIdx.x < SS) g_prog[threadIdx.x] = 0;   // reset progress
    if (bb == 0 && threadIdx.x == 255) g_ticket = 0;            // reset tickets

    __shared__ __align__(16) float se[16][XX];

    const bool is64 = ((xraw[1] | xraw[3] | xraw[5] | xraw[7] | xraw[9]) == 0) &&
                      ((xraw[0] | xraw[2] | xraw[4] | xraw[6] | xraw[8]) != 0);

    const int m0 = bb * 16;
    for (int i = threadIdx.x; i < 16 * (XX / 4); i += 256) {
        int r = i >> 5, c = i & 31;
        int m = m0 + r;
        int tok = is64 ? xraw[2 * m] : xraw[m];
        ((float4*)se[r])[c] = ((const float4*)(emb + (long long)tok * XX))[c];
    }
    __syncthreads();

    const int j = threadIdx.x;
    const float bias = b_ih[j] + b_hh[j];
    float acc[16];
#pragma unroll
    for (int r = 0; r < 16; r++) acc[r] = bias;

    const float* wr = W_ih + j * XX;
#pragma unroll 4
    for (int k = 0; k < XX; k += 4) {
        float4 w = *(const float4*)(wr + k);
#pragma unroll
        for (int r = 0; r < 16; r++) {
            float4 e = *(const float4*)&se[r][k];
            acc[r] = fmaf(w.x, e.x, fmaf(w.y, e.y, fmaf(w.z, e.z, fmaf(w.w, e.w, acc[r]))));
        }
    }
#pragma unroll
    for (int r = 0; r < 16; r++)
        g_xin[(m0 + r) * HH + j] = acc[r];
}

// ============================================================================
// prep_b: W_aff -> fp16  (stream s2, concurrent with prep_a; precedes consumers)
// ============================================================================
__global__ void __launch_bounds__(256)
prep_b(const float* __restrict__ Wa)
{
    int idx = blockIdx.x * 256 + threadIdx.x;   // NPAD * 64
    int n  = idx >> 6;
    int k4 = (idx & 63) << 2;
    float4 w = make_float4(0.f, 0.f, 0.f, 0.f);
    if (n < VV) w = *(const float4*)(Wa + (size_t)n * 256 + k4);
    __half* p = g_B2 + (size_t)n * 256 + k4;
    p[0] = __float2half_rn(w.x);
    p[1] = __float2half_rn(w.y);
    p[2] = __float2half_rn(w.z);
    p[3] = __float2half_rn(w.w);
}

// ============================================================================
// Persistent GEMM consumer loop — single-pass fp16, K = 256, 4 chunks of 64.
// ============================================================================
#define RNN_W_F2   (128 * 64)            // float2: quarter of W (64 KB)
#define RNN_HB_F2  (2 * 4 * 256)         // [buf][rq][k]  (16 KB)
#define HALF_TILE 16384
#define STAGE_BYTES (2 * HALF_TILE)      // A + B
#define NSTAGE 3
#define SMEM_TILES (NSTAGE * STAGE_BYTES)   // 98304 (rnn scan uses 88 KB subset)
#define NB_RNN 64
#define NB_GEMM 232
#define NCHUNK 4

__device__ void consume_tiles(const float* __restrict__ ba, float* __restrict__ C,
                              char* smem, int tid)
{
    const uint32_t sb = smem_u32(smem);
    const int wid  = tid >> 5;
    const int lane = tid & 31;

    uint32_t t_sw[4];
    int l_row[4], l_c[4];
#pragma unroll
    for (int i = 0; i < 4; i++) {
        int idx = i * 256 + tid;
        l_row[i] = idx >> 3; l_c[i] = idx & 7;
        t_sw[i] = SW128(l_row[i] * 128 + l_c[i] * 16);
    }

    const int wm0 = (wid >> 1) * 32;
    const int wn0 = (wid & 1) * 64;
    const int a_row  = wm0 + (lane & 7) + ((lane & 8) ? 8 : 0);
    const int a_koff = (lane & 16) ? 16 : 0;
    const int b_row  = wn0 + (lane & 7) + ((lane & 16) ? 8 : 0);
    const int b_koff = (lane & 8) ? 16 : 0;
    const int lm = lane >> 2;
    const int lq = (lane & 3) * 2;

    __shared__ int s_ticket;

    for (;;) {
        if (tid == 0) s_ticket = atomicAdd(&g_ticket, 1);
        __syncthreads();
        const int ticket = s_ticket;
        __syncthreads();
        if (ticket >= N_TICKETS) return;

        const int tT = ticket / NT_N;
        const int bn = (ticket % NT_N) * 128;
        const int bm = tT * 128;

        if (tid == 0) {
            while (ld_acq(&g_prog[tT]) < NB_RNN) __nanosleep(128);
        }
        __syncthreads();

        const __half* a_src[4];
        const __half* b_src[4];
#pragma unroll
        for (int i = 0; i < 4; i++) {
            a_src[i] = g_A2 + (size_t)(bm + l_row[i]) * 256 + l_c[i] * 8;
            b_src[i] = g_B2 + (size_t)(bn + l_row[i]) * 256 + l_c[i] * 8;
        }

        float acc[2][8][4];
#pragma unroll
        for (int mt = 0; mt < 2; mt++)
#pragma unroll
            for (int nt = 0; nt < 8; nt++)
#pragma unroll
                for (int q = 0; q < 4; q++) acc[mt][nt][q] = 0.f;

        auto prefetch = [&](int ch) {
            const int off = ch * 64;
            const uint32_t base = sb + (ch % NSTAGE) * STAGE_BYTES;
#pragma unroll
            for (int i = 0; i < 4; i++) cp_async16(base + t_sw[i], a_src[i] + off);
#pragma unroll
            for (int i = 0; i < 4; i++) cp_async16(base + HALF_TILE + t_sw[i], b_src[i] + off);
            asm volatile("cp.async.commit_group;" ::: "memory");
        };

        prefetch(0);
        prefetch(1);

#pragma unroll 1
        for (int ch = 0; ch < NCHUNK; ++ch) {
            if (ch < NCHUNK - 1) asm volatile("cp.async.wait_group 1;" ::: "memory");
            else                 asm volatile("cp.async.wait_group 0;" ::: "memory");
            __syncthreads();
            if (ch + 2 < NCHUNK) prefetch(ch + 2);

            const uint32_t Ab = sb + (ch % NSTAGE) * STAGE_BYTES;
            const uint32_t Bb = Ab + HALF_TILE;

#pragma unroll
            for (int ks = 0; ks < 4; ++ks) {
                const int kb = ks * 32;
                uint32_t a[2][4], b[4][4];
#pragma unroll
                for (int mt = 0; mt < 2; mt++)
                    ldsm4(a[mt], Ab + SW128((a_row + mt * 16) * 128 + kb + a_koff));
#pragma unroll
                for (int p = 0; p < 4; p++)
                    ldsm4(b[p], Bb + SW128((b_row + p * 16) * 128 + kb + b_koff));
#pragma unroll
                for (int mt = 0; mt < 2; mt++)
#pragma unroll
                    for (int p = 0; p < 4; p++) {
                        mma16816(acc[mt][2 * p + 0], a[mt], b[p][0], b[p][1]);
                        mma16816(acc[mt][2 * p + 1], a[mt], b[p][2], b[p][3]);
                    }
            }
        }

        // epilogue: C row for tile-local row b is m_orig = b*SS + tT
#pragma unroll
        for (int nt = 0; nt < 8; nt++) {
            const int gcol = bn + wn0 + nt * 8 + lq;
            if (gcol >= VV) continue;
            const float2 bv = *(const float2*)(ba + gcol);
#pragma unroll
            for (int mt = 0; mt < 2; mt++) {
                const int brow = wm0 + mt * 16 + lm;             // batch index
                float* c0 = C + ((size_t)brow * SS + tT) * VV + gcol;
                float2 o0 = make_float2(acc[mt][nt][0] + bv.x, acc[mt][nt][1] + bv.y);
                float2 o1 = make_float2(acc[mt][nt][2] + bv.x, acc[mt][nt][3] + bv.y);
                *(float2*)c0                         = o0;
                *(float2*)(c0 + (size_t)8 * SS * VV) = o1;       // brow+8
            }
        }
        __syncthreads();
    }
}

// ============================================================================
// RNN kernel (cluster-4, 64 CTAs) — k-split matvec:
//   Phase 1: thread (ks = tid>>6, jl = tid&63) computes partial sums over
//            k-quarter ks for ALL 4 row-pairs (W column read exactly once).
//   Phase 2: thread (rq = tid>>6, jl) reduces 4 partials, adds x, tanh, stores
//            (identical pointer layout to the previous rq-mapped code).
// smem: W 64 KB | hb 16 KB | sred 8 KB = 88 KB.
// ============================================================================
__global__ void __launch_bounds__(256, 2) __cluster_dims__(4, 1, 1)
rnn_then_consume(const float* __restrict__ ba, float* __restrict__ C)
{
    extern __shared__ __align__(1024) char smem[];
    const int bid = blockIdx.x;
    const int tid = threadIdx.x;

    {
        float2* wsp  = (float2*)smem;                         // [k2*64 + jl]
        float2* hb   = (float2*)smem + RNN_W_F2;              // [(buf*4+rq)*256 + k]
        double* sred = (double*)((float2*)smem + RNN_W_F2 + RNN_HB_F2); // [ks][rq][jl]
        const uint32_t hb_addr = smem_u32(hb);

        const int ks   = tid >> 6;              // k-quarter (ph1) == rowpair (ph2)
        const int jl   = tid & 63;
        const uint32_t rank = bid & 3;
        const int jg   = rank * 64 + jl;        // global output column
        const int b0   = (bid >> 2) * 8;        // 8 batch rows per cluster

        for (int i = tid; i < RNN_W_F2; i += 256) {
            int k2 = i >> 6, j = i & 63;
            int jgl = rank * 64 + j;
            wsp[i] = make_float2(g_WT[(2 * k2) * HH + jgl],
                                 g_WT[(2 * k2 + 1) * HH + jgl]);
        }
        for (int i = tid; i < 4 * 256; i += 256) hb[i] = make_float2(0.f, 0.f);

        asm volatile("barrier.cluster.arrive.aligned;" ::: "memory");
        asm volatile("barrier.cluster.wait.aligned;" ::: "memory");

        const int r0 = b0 + 2 * ks;             // phase-2 rows
        const float* x0p = g_xin + (size_t)r0 * SS * HH + jg;
        const float* x1p = g_xin + (size_t)(r0 + 1) * SS * HH + jg;
        __half* a0p = g_A2 + (size_t)r0 * 256 + jg;        // + t*BB*256
        __half* a1p = g_A2 + (size_t)(r0 + 1) * 256 + jg;

        const float2* wp = wsp + jl;
        const uint32_t p1 = rank ^ 1, p2 = rank ^ 2, p3 = rank ^ 3;

        float xa = x0p[0], xb = x1p[0];
        int cur = 0;
        for (int t = 0; t < SS; ++t) {
            // ---------- phase 1: partial matvec over k-quarter ks ----------
            double acc0 = 0.0, acc1 = 0.0, acc2 = 0.0, acc3 = 0.0;
            {
                const double2* h0c = (const double2*)(hb + (cur * 4 + 0) * 256);
                const double2* h1c = (const double2*)(hb + (cur * 4 + 1) * 256);
                const double2* h2c = (const double2*)(hb + (cur * 4 + 2) * 256);
                const double2* h3c = (const double2*)(hb + (cur * 4 + 3) * 256);
                const int k2b = ks * 32;
#pragma unroll 8
                for (int k2i = 0; k2i < 32; ++k2i) {
                    const int k2 = k2b + k2i;
                    float2 wv = wp[k2 * 64];
                    double we = dup2(wv.x), wo = dup2(wv.y);
                    double2 ha = h0c[k2]; ffma2(acc0, we, ha.x); ffma2(acc0, wo, ha.y);
                    double2 hbv = h1c[k2]; ffma2(acc1, we, hbv.x); ffma2(acc1, wo, hbv.y);
                    double2 hcv = h2c[k2]; ffma2(acc2, we, hcv.x); ffma2(acc2, wo, hcv.y);
                    double2 hdv = h3c[k2]; ffma2(acc3, we, hdv.x); ffma2(acc3, wo, hdv.y);
                }
            }
            sred[(ks * 4 + 0) * 64 + jl] = acc0;
            sred[(ks * 4 + 1) * 64 + jl] = acc1;
            sred[(ks * 4 + 2) * 64 + jl] = acc2;
            sred[(ks * 4 + 3) * 64 + jl] = acc3;
            __syncthreads();

            // ---------- phase 2: reduce across k-quarters, activate ----------
            double s = fadd2(fadd2(sred[(0 * 4 + ks) * 64 + jl],
                                   sred[(1 * 4 + ks) * 64 + jl]),
                             fadd2(sred[(2 * 4 + ks) * 64 + jl],
                                   sred[(3 * 4 + ks) * 64 + jl]));
            float2 f = unpk(fadd2(s, pk2(xa, xb)));
            float h0 = tanhf(f.x), h1 = tanhf(f.y);

            if (t + 1 < SS) {
                xa = x0p[(size_t)(t + 1) * HH];
                xb = x1p[(size_t)(t + 1) * HH];
            }

            const int nxt = cur ^ 1;
            const long long hp = __double_as_longlong(pk2(h0, h1));
            uint32_t loc = hb_addr + (uint32_t)(((nxt * 4 + ks) * 256 + jg) * 8);
            asm volatile("st.shared.b64 [%0], %1;" :: "r"(loc), "l"(hp) : "memory");
            asm volatile(
                "{\n\t.reg .b32 ra;\n\t"
                "mapa.shared::cluster.u32 ra, %0, %1;\n\t"
                "st.shared::cluster.b64 [ra], %2;\n\t"
                "mapa.shared::cluster.u32 ra, %0, %3;\n\t"
                "st.shared::cluster.b64 [ra], %2;\n\t"
                "mapa.shared::cluster.u32 ra, %0, %4;\n\t"
                "st.shared::cluster.b64 [ra], %2;\n\t}"
                :: "r"(loc), "r"(p1), "l"(hp), "r"(p2), "r"(p3) : "memory");

            a0p[(size_t)t * (BB * 256)] = __float2half_rn(h0);
            a1p[(size_t)t * (BB * 256)] = __float2half_rn(h1);

            asm volatile("barrier.cluster.arrive.aligned;" ::: "memory");
            asm volatile("barrier.cluster.wait.aligned;" ::: "memory");
            if (tid == 0) red_release(&g_prog[t]);
            cur = nxt;
        }
    }
    __syncthreads();
    // Scan done: convert this CTA into a gemm consumer (reuses smem).
    consume_tiles(ba, C, smem, tid);
}

// ============================================================================
// Pure consumer kernel (no cluster -> full scheduling flexibility)
// ============================================================================
__global__ void __launch_bounds__(256, 2)
gemm_consume(const float* __restrict__ ba, float* __restrict__ C)
{
    extern __shared__ __align__(1024) char smem[];
    consume_tiles(ba, C, smem, threadIdx.x);
}

// ============================================================================
extern "C" void kernel_launch(void* const* d_in, const int* in_sizes, int n_in,
                              void* d_out, int out_size)
{
    const int*   x     = (const int*)  d_in[0];
    const float* emb   = (const float*)d_in[1];
    const float* W_ih  = (const float*)d_in[2];
    const float* W_hh  = (const float*)d_in[3];
    const float* b_ih  = (const float*)d_in[4];
    const float* b_hh  = (const float*)d_in[5];
    const float* W_aff = (const float*)d_in[6];
    const float* b_aff = (const float*)d_in[7];
    float* out = (float*)d_out;

    static cudaStream_t s2 = nullptr;
    static cudaEvent_t evF = nullptr, evA = nullptr, evB = nullptr;
    if (s2 == nullptr) {
        cudaStreamCreateWithFlags(&s2, cudaStreamNonBlocking);
        cudaEventCreateWithFlags(&evF, cudaEventDisableTiming);
        cudaEventCreateWithFlags(&evA, cudaEventDisableTiming);
        cudaEventCreateWithFlags(&evB, cudaEventDisableTiming);
        cudaFuncSetAttribute(rnn_then_consume,
                             cudaFuncAttributeMaxDynamicSharedMemorySize, SMEM_TILES);
        cudaFuncSetAttribute(gemm_consume,
                             cudaFuncAttributeMaxDynamicSharedMemorySize, SMEM_TILES);
    }

    // fork s2 off the capture stream
    cudaEventRecord(evF, 0);
    cudaStreamWaitEvent(s2, evF, 0);

    prep_a<<<NB_PREPA, 256>>>(x, emb, W_ih, b_ih, b_hh, W_hh);   // stream 0
    prep_b<<<NB_PREPB, 256, 0, s2>>>(W_aff);                     // stream s2 (concurrent)

    cudaEventRecord(evA, 0);                 // prep_a (incl. sync resets) done
    cudaStreamWaitEvent(s2, evA, 0);         // consumers need resets before spinning

    rnn_then_consume<<<NB_RNN, 256, SMEM_TILES>>>(b_aff, out);          // stream 0
    gemm_consume<<<NB_GEMM, 256, SMEM_TILES, s2>>>(b_aff, out);         // stream s2

    // join
    cudaEventRecord(evB, s2);
    cudaStreamWaitEvent(0, evB, 0);
}